// round 1
// baseline (speedup 1.0000x reference)
#include <cuda_runtime.h>
#include <math.h>

// Problem constants
#define Bn 256
#define Cn 384
#define Dn 384
static const int Mtot = Bn * Cn;               // 98304
static const float INV_SQRT_D = 0.05103103630798288f; // 1/sqrt(384)

static const size_t ELEMS = (size_t)Bn * Cn * Dn;  // 37,748,736

// Scratch (device globals: allocation-free)
__device__ float g_Q[ELEMS];
__device__ float g_K[ELEMS];
__device__ float g_V[ELEMS];
__device__ float g_S[(size_t)Bn * Cn * Cn];

// ---------------------------------------------------------------------------
// Generic 128x128x16 register-blocked SGEMM core.
// MODE 0: C = A[M,K] * B[N,K]^T + bias       (QKV projection, unbatched)
// MODE 1: C = A[M,K] * B[N,K]^T, causal mask + scale epilogue (batched, z=batch)
// MODE 2: C = A[M,K] * B[K,N]                (P @ V, batched, z=batch)
// ---------------------------------------------------------------------------
template <int MODE>
__global__ __launch_bounds__(256)
void gemm_kernel(const float* __restrict__ Aall,
                 const float* __restrict__ Ball,
                 const float* __restrict__ bias,
                 float* __restrict__ Call,
                 int M, int N, int K)
{
    __shared__ float As[16][128];
    __shared__ float Bs[16][128];

    const float* A;
    const float* Bm;
    float* Co;
    if (MODE == 0) {
        A = Aall; Bm = Ball; Co = Call;
    } else {
        int bz = blockIdx.z;
        A  = Aall + (size_t)bz * M * K;
        Bm = (MODE == 1) ? (Ball + (size_t)bz * N * K)
                         : (Ball + (size_t)bz * K * N);
        Co = Call + (size_t)bz * M * N;
    }

    const int m0 = blockIdx.y * 128;
    const int n0 = blockIdx.x * 128;
    const int tid = threadIdx.x;
    const int tx = tid & 15;   // 0..15 -> n
    const int ty = tid >> 4;   // 0..15 -> m

    // loader indices (NT style: 128 rows x 16 cols)
    const int arow = tid >> 2;  // 0..63
    const int ac4  = tid & 3;   // 0..3
    // loader indices (NN style: 16 rows x 128 cols)
    const int brow = tid >> 5;  // 0..7
    const int bc4  = tid & 31;  // 0..31

    float acc[8][8];
#pragma unroll
    for (int i = 0; i < 8; i++)
#pragma unroll
        for (int j = 0; j < 8; j++) acc[i][j] = 0.0f;

    for (int k0 = 0; k0 < K; k0 += 16) {
        // ---- load A tile (rows m0.., cols k0..k0+15), transpose into As[k][m]
#pragma unroll
        for (int r = 0; r < 2; r++) {
            int row = arow + r * 64;
            float4 v = *(const float4*)&A[(size_t)(m0 + row) * K + k0 + ac4 * 4];
            As[ac4 * 4 + 0][row] = v.x;
            As[ac4 * 4 + 1][row] = v.y;
            As[ac4 * 4 + 2][row] = v.z;
            As[ac4 * 4 + 3][row] = v.w;
        }
        // ---- load B tile
        if (MODE != 2) {
            // B is [N,K]: rows n0.., cols k0..k0+15 -> Bs[k][n]
#pragma unroll
            for (int r = 0; r < 2; r++) {
                int row = arow + r * 64;
                float4 v = *(const float4*)&Bm[(size_t)(n0 + row) * K + k0 + ac4 * 4];
                Bs[ac4 * 4 + 0][row] = v.x;
                Bs[ac4 * 4 + 1][row] = v.y;
                Bs[ac4 * 4 + 2][row] = v.z;
                Bs[ac4 * 4 + 3][row] = v.w;
            }
        } else {
            // B is [K,N]: rows k0..k0+15, cols n0.. -> Bs[k][n]
#pragma unroll
            for (int r = 0; r < 2; r++) {
                int row = brow + r * 8;
                float4 v = *(const float4*)&Bm[(size_t)(k0 + row) * N + n0 + bc4 * 4];
                *(float4*)&Bs[row][bc4 * 4] = v;
            }
        }
        __syncthreads();

#pragma unroll
        for (int kk = 0; kk < 16; kk++) {
            float a[8], b[8];
#pragma unroll
            for (int i = 0; i < 8; i++) a[i] = As[kk][ty * 8 + i];
#pragma unroll
            for (int j = 0; j < 8; j++) b[j] = Bs[kk][tx * 8 + j];
#pragma unroll
            for (int i = 0; i < 8; i++)
#pragma unroll
                for (int j = 0; j < 8; j++)
                    acc[i][j] += a[i] * b[j];
        }
        __syncthreads();
    }

    // ---- epilogue
#pragma unroll
    for (int i = 0; i < 8; i++) {
        int m = m0 + ty * 8 + i;
#pragma unroll
        for (int j = 0; j < 8; j++) {
            int n = n0 + tx * 8 + j;
            float v = acc[i][j];
            if (MODE == 0) v += bias[n];
            if (MODE == 1) {
                v = (v + (n <= m ? 0.0f : -100000.0f)) * INV_SQRT_D;
            }
            Co[(size_t)m * N + n] = v;
        }
    }
}

// ---------------------------------------------------------------------------
// In-place row softmax: warp per row of 384 floats (12 per lane).
// ---------------------------------------------------------------------------
__global__ __launch_bounds__(256)
void softmax_kernel(float* __restrict__ S)
{
    const int row = blockIdx.x * 8 + (threadIdx.x >> 5);
    const int lane = threadIdx.x & 31;
    float* p = S + (size_t)row * Cn + lane * 12;

    float4 v0 = *(float4*)(p);
    float4 v1 = *(float4*)(p + 4);
    float4 v2 = *(float4*)(p + 8);

    float mx = fmaxf(fmaxf(fmaxf(v0.x, v0.y), fmaxf(v0.z, v0.w)),
               fmaxf(fmaxf(fmaxf(v1.x, v1.y), fmaxf(v1.z, v1.w)),
                     fmaxf(fmaxf(v2.x, v2.y), fmaxf(v2.z, v2.w))));
#pragma unroll
    for (int o = 16; o > 0; o >>= 1)
        mx = fmaxf(mx, __shfl_xor_sync(0xffffffffu, mx, o));

    v0.x = expf(v0.x - mx); v0.y = expf(v0.y - mx);
    v0.z = expf(v0.z - mx); v0.w = expf(v0.w - mx);
    v1.x = expf(v1.x - mx); v1.y = expf(v1.y - mx);
    v1.z = expf(v1.z - mx); v1.w = expf(v1.w - mx);
    v2.x = expf(v2.x - mx); v2.y = expf(v2.y - mx);
    v2.z = expf(v2.z - mx); v2.w = expf(v2.w - mx);

    float sum = (v0.x + v0.y + v0.z + v0.w)
              + (v1.x + v1.y + v1.z + v1.w)
              + (v2.x + v2.y + v2.z + v2.w);
#pragma unroll
    for (int o = 16; o > 0; o >>= 1)
        sum += __shfl_xor_sync(0xffffffffu, sum, o);

    float inv = 1.0f / sum;
    v0.x *= inv; v0.y *= inv; v0.z *= inv; v0.w *= inv;
    v1.x *= inv; v1.y *= inv; v1.z *= inv; v1.w *= inv;
    v2.x *= inv; v2.y *= inv; v2.z *= inv; v2.w *= inv;

    *(float4*)(p)     = v0;
    *(float4*)(p + 4) = v1;
    *(float4*)(p + 8) = v2;
}

// ---------------------------------------------------------------------------
extern "C" void kernel_launch(void* const* d_in, const int* in_sizes, int n_in,
                              void* d_out, int out_size)
{
    const float* z  = (const float*)d_in[0];
    const float* Wq = (const float*)d_in[1];
    const float* bq = (const float*)d_in[2];
    const float* Wk = (const float*)d_in[3];
    const float* bk = (const float*)d_in[4];
    const float* Wv = (const float*)d_in[5];
    const float* bv = (const float*)d_in[6];
    float* out = (float*)d_out;

    float *Qp, *Kp, *Vp, *Sp;
    cudaGetSymbolAddress((void**)&Qp, g_Q);
    cudaGetSymbolAddress((void**)&Kp, g_K);
    cudaGetSymbolAddress((void**)&Vp, g_V);
    cudaGetSymbolAddress((void**)&Sp, g_S);

    dim3 blk(256);

    // QKV projections: [98304,384] = z @ W^T + b
    dim3 gproj(Dn / 128, Mtot / 128, 1);
    gemm_kernel<0><<<gproj, blk>>>(z, Wq, bq, Qp, Mtot, Dn, Dn);
    gemm_kernel<0><<<gproj, blk>>>(z, Wk, bk, Kp, Mtot, Dn, Dn);
    gemm_kernel<0><<<gproj, blk>>>(z, Wv, bv, Vp, Mtot, Dn, Dn);

    // Scores: per-batch S = Q K^T, causal mask + 1/sqrt(D), batched over z
    dim3 gatt(Cn / 128, Cn / 128, Bn);
    gemm_kernel<1><<<gatt, blk>>>(Qp, Kp, nullptr, Sp, Cn, Cn, Dn);

    // Row softmax in place (98304 rows, 8 rows/block)
    softmax_kernel<<<(Bn * Cn) / 8, blk>>>(Sp);

    // Output: per-batch O = P @ V, written directly to d_out
    gemm_kernel<2><<<gatt, blk>>>(Sp, Vp, nullptr, out, Cn, Dn, Cn);
}

// round 3
// speedup vs baseline: 2.5107x; 2.5107x over previous
#include <cuda_runtime.h>
#include <cuda_bf16.h>
#include <math.h>
#include <stdint.h>

#define NTH 256
#define Cn 384
#define Dn 384
#define BSTRIDE 147456           // 384*384 per-batch stride
static const float INV_SQRT_D = 0.05103103630798288f; // 1/sqrt(384)

__device__ float g_Q[37748736];
__device__ float g_K[37748736];
__device__ float g_V[37748736];
__device__ float g_S[37748736];

// ---- dynamic smem layout: 4 regions, each 2 buffers x 8KB ----
#define A_HI 0
#define A_LO 16384
#define B_HI 32768
#define B_LO 49152
#define SMEM_BYTES 65536

#define MMA(d, a, b) \
    asm volatile("mma.sync.aligned.m16n8k16.row.col.f32.bf16.bf16.f32 " \
        "{%0,%1,%2,%3},{%4,%5,%6,%7},{%8,%9},{%0,%1,%2,%3};" \
        : "+f"((d)[0]), "+f"((d)[1]), "+f"((d)[2]), "+f"((d)[3]) \
        : "r"((a).x), "r"((a).y), "r"((a).z), "r"((a).w), \
          "r"((b).x), "r"((b).y))

__device__ __forceinline__ void split2(float x, float y,
                                       uint32_t& hi, uint32_t& lo) {
    __nv_bfloat16 hx = __float2bfloat16(x);
    __nv_bfloat16 hy = __float2bfloat16(y);
    float lx = x - __bfloat162float(hx);
    float ly = y - __bfloat162float(hy);
    __nv_bfloat162 h2 = __halves2bfloat162(hx, hy);
    __nv_bfloat162 l2 = __floats2bfloat162_rn(lx, ly);
    hi = reinterpret_cast<uint32_t&>(h2);
    lo = reinterpret_cast<uint32_t&>(l2);
}

// ---------------------------------------------------------------------------
// MODE 0: QKV projection. grid(9, 768). bx -> (w, ntile); by -> mtile.
// MODE 1: scores: S = (Q K^T + mask) / sqrt(D). grid(3, 3, 256).
// MODE 2: out = P V. grid(3, 3, 256); K-loop truncated at (mt+1)*128.
// ---------------------------------------------------------------------------
template <int MODE>
__global__ __launch_bounds__(NTH, 1) void mma_gemm(
    const float* __restrict__ Aall,
    const float* __restrict__ B0, const float* __restrict__ B1,
    const float* __restrict__ B2,
    const float* __restrict__ bias0, const float* __restrict__ bias1,
    const float* __restrict__ bias2,
    float* __restrict__ O0, float* __restrict__ O1, float* __restrict__ O2)
{
    extern __shared__ __align__(16) char smbuf[];
    char* sm = smbuf;
    const int tid = threadIdx.x;
    const int lane = tid & 31;
    const int wid = tid >> 5;
    const int wm = wid >> 2;   // 0..1
    const int wn = wid & 3;    // 0..3

    const float* A;
    const float* Bp;
    const float* bias = nullptr;
    float* Co;
    int m0, n0, NKT, mt = 0, nt = 0;

    if (MODE == 0) {
        int w = blockIdx.x / 3;
        nt = blockIdx.x % 3;
        m0 = blockIdx.y * 128;
        n0 = nt * 128;
        A = Aall;
        Bp = (w == 0) ? B0 : (w == 1) ? B1 : B2;
        bias = (w == 0) ? bias0 : (w == 1) ? bias1 : bias2;
        Co = (w == 0) ? O0 : (w == 1) ? O1 : O2;
        NKT = 12;
    } else {
        nt = blockIdx.x; mt = blockIdx.y;
        m0 = mt * 128; n0 = nt * 128;
        A  = Aall + (size_t)blockIdx.z * BSTRIDE;
        Bp = B0   + (size_t)blockIdx.z * BSTRIDE;
        Co = O0   + (size_t)blockIdx.z * BSTRIDE;
        NKT = (MODE == 2) ? (mt + 1) * 4 : 12;
        if (MODE == 1 && nt > mt) {
            // fully masked tile: write constant; softmax turns it into 0
            const float MV = -100000.0f * INV_SQRT_D;
            for (int idx = tid; idx < 128 * 128; idx += NTH) {
                int r = idx >> 7, c = idx & 127;
                Co[(size_t)(m0 + r) * Cn + n0 + c] = MV;
            }
            return;
        }
    }

    // ---- loader precompute (A and B modes 0/1 share [row][k] shape) ----
    const int abase = tid >> 4;   // 0..15 (row base)
    const int akp   = tid & 15;   // 0..15 (k-pair)
    const int aslab = akp >> 3;
    const int alane = (abase & 7) * 4 + (akp & 3);
    const int areg  = ((akp >> 2) & 1) * 2 + ((abase >> 3) & 1);
    const int offA0 = aslab * 4096 + alane * 16 + areg * 4;       // + i*512
    const int breg  = (akp >> 2) & 1;
    const int offB0 = aslab * 4096 + (abase >> 3) * 256 + alane * 8 + breg * 4; // + i*512

    const float* gA = A + (size_t)(m0 + abase) * 384 + akp * 2;
    const float* gB = (MODE != 2)
        ? (Bp + (size_t)(n0 + abase) * 384 + akp * 2)
        : nullptr;
    // mode-2 V loader: [k][n], n contiguous
    const int vn  = tid & 127;
    const int vkb = tid >> 7;   // 0/1
    const float* gV = (MODE == 2) ? (Bp + (size_t)vkb * 384 + n0 + vn) : nullptr;

    float2 pa[8], pb[8];
    float  pv[16];

    // ---- prefetch kt = 0 ----
#pragma unroll
    for (int i = 0; i < 8; i++) pa[i] = *(const float2*)(gA + i * 6144);
    if (MODE != 2) {
#pragma unroll
        for (int i = 0; i < 8; i++) pb[i] = *(const float2*)(gB + i * 6144);
    } else {
#pragma unroll
        for (int j = 0; j < 16; j++) pv[j] = gV[j * 768];
    }

    // ---- store kt = 0 into buf 0 ----
    {
        char* dst = sm;
#pragma unroll
        for (int i = 0; i < 8; i++) {
            uint32_t hi, lo;
            split2(pa[i].x, pa[i].y, hi, lo);
            *(uint32_t*)(dst + A_HI + offA0 + i * 512) = hi;
            *(uint32_t*)(dst + A_LO + offA0 + i * 512) = lo;
        }
        if (MODE != 2) {
#pragma unroll
            for (int i = 0; i < 8; i++) {
                uint32_t hi, lo;
                split2(pb[i].x, pb[i].y, hi, lo);
                *(uint32_t*)(dst + B_HI + offB0 + i * 512) = hi;
                *(uint32_t*)(dst + B_LO + offB0 + i * 512) = lo;
            }
        } else {
#pragma unroll
            for (int j = 0; j < 16; j++) {
                int k = vkb + 2 * j;
                int off = (k >> 4) * 4096 + (vn >> 3) * 256 +
                          ((vn & 7) * 4 + (j & 3)) * 8 + ((k >> 3) & 1) * 4 +
                          vkb * 2;
                __nv_bfloat16 h = __float2bfloat16(pv[j]);
                float l = pv[j] - __bfloat162float(h);
                *(__nv_bfloat16*)(dst + B_HI + off) = h;
                *(__nv_bfloat16*)(dst + B_LO + off) = __float2bfloat16(l);
            }
        }
    }
    __syncthreads();

    float acc[4][4][4];
#pragma unroll
    for (int i = 0; i < 4; i++)
#pragma unroll
        for (int j = 0; j < 4; j++)
#pragma unroll
            for (int r = 0; r < 4; r++) acc[i][j][r] = 0.0f;

    // ---- main loop ----
    for (int kt = 0; kt < NKT; kt++) {
        const int buf = kt & 1;
        const bool more = (kt + 1) < NKT;
        if (more) {
            const float* a2 = gA + (kt + 1) * 32;
#pragma unroll
            for (int i = 0; i < 8; i++) pa[i] = *(const float2*)(a2 + i * 6144);
            if (MODE != 2) {
                const float* b2 = gB + (kt + 1) * 32;
#pragma unroll
                for (int i = 0; i < 8; i++) pb[i] = *(const float2*)(b2 + i * 6144);
            } else {
                const float* v2 = gV + (size_t)(kt + 1) * 32 * 384;
#pragma unroll
                for (int j = 0; j < 16; j++) pv[j] = v2[j * 768];
            }
        }

        // ---- compute on buf ----
        {
            char* base = sm + buf * 8192;
#pragma unroll
            for (int s = 0; s < 2; s++) {
                uint4 ah[4], al[4];
                uint2 bh[4], bl[4];
#pragma unroll
                for (int i = 0; i < 4; i++) {
                    int off = s * 4096 + (wm * 4 + i) * 512 + lane * 16;
                    ah[i] = *(const uint4*)(base + A_HI + off);
                    al[i] = *(const uint4*)(base + A_LO + off);
                }
#pragma unroll
                for (int j = 0; j < 4; j++) {
                    int off = s * 4096 + (wn * 4 + j) * 256 + lane * 8;
                    bh[j] = *(const uint2*)(base + B_HI + off);
                    bl[j] = *(const uint2*)(base + B_LO + off);
                }
#pragma unroll
                for (int i = 0; i < 4; i++)
#pragma unroll
                    for (int j = 0; j < 4; j++) {
                        MMA(acc[i][j], ah[i], bh[j]);
                        MMA(acc[i][j], ah[i], bl[j]);
                        MMA(acc[i][j], al[i], bh[j]);
                    }
            }
        }

        if (more) {
            char* dst = sm + (buf ^ 1) * 8192;
#pragma unroll
            for (int i = 0; i < 8; i++) {
                uint32_t hi, lo;
                split2(pa[i].x, pa[i].y, hi, lo);
                *(uint32_t*)(dst + A_HI + offA0 + i * 512) = hi;
                *(uint32_t*)(dst + A_LO + offA0 + i * 512) = lo;
            }
            if (MODE != 2) {
#pragma unroll
                for (int i = 0; i < 8; i++) {
                    uint32_t hi, lo;
                    split2(pb[i].x, pb[i].y, hi, lo);
                    *(uint32_t*)(dst + B_HI + offB0 + i * 512) = hi;
                    *(uint32_t*)(dst + B_LO + offB0 + i * 512) = lo;
                }
            } else {
#pragma unroll
                for (int j = 0; j < 16; j++) {
                    int k = vkb + 2 * j;
                    int off = (k >> 4) * 4096 + (vn >> 3) * 256 +
                              ((vn & 7) * 4 + (j & 3)) * 8 + ((k >> 3) & 1) * 4 +
                              vkb * 2;
                    __nv_bfloat16 h = __float2bfloat16(pv[j]);
                    float l = pv[j] - __bfloat162float(h);
                    *(__nv_bfloat16*)(dst + B_HI + off) = h;
                    *(__nv_bfloat16*)(dst + B_LO + off) = __float2bfloat16(l);
                }
            }
        }
        __syncthreads();
    }

    // ---- epilogue: registers -> gmem ----
    const int g = lane >> 2, t = lane & 3;
#pragma unroll
    for (int i = 0; i < 4; i++) {
        const int r0 = m0 + wm * 64 + i * 16 + g;   // row (local for modes 1/2)
#pragma unroll
        for (int j = 0; j < 4; j++) {
            const int c0 = n0 + wn * 32 + j * 8 + t * 2;
            float d0 = acc[i][j][0], d1 = acc[i][j][1];
            float d2 = acc[i][j][2], d3 = acc[i][j][3];
            if (MODE == 0) {
                float b0 = bias[c0], b1 = bias[c0 + 1];
                d0 += b0; d1 += b1; d2 += b0; d3 += b1;
            }
            if (MODE == 1) {
                const int q0 = r0, q1 = r0 + 8;
                d0 = (d0 + ((c0     <= q0) ? 0.0f : -100000.0f)) * INV_SQRT_D;
                d1 = (d1 + ((c0 + 1 <= q0) ? 0.0f : -100000.0f)) * INV_SQRT_D;
                d2 = (d2 + ((c0     <= q1) ? 0.0f : -100000.0f)) * INV_SQRT_D;
                d3 = (d3 + ((c0 + 1 <= q1) ? 0.0f : -100000.0f)) * INV_SQRT_D;
            }
            float* o = Co + (size_t)r0 * 384 + c0;
            o[0] = d0; o[1] = d1;
            o[8 * 384]     = d2;
            o[8 * 384 + 1] = d3;
        }
    }
}

// ---------------------------------------------------------------------------
// In-place row softmax: warp per row of 384 floats (12 per lane).
// ---------------------------------------------------------------------------
__global__ __launch_bounds__(256) void softmax_kernel(float* __restrict__ S)
{
    const int row = blockIdx.x * 8 + (threadIdx.x >> 5);
    const int lane = threadIdx.x & 31;
    float* p = S + (size_t)row * Cn + lane * 12;

    float4 v0 = *(float4*)(p);
    float4 v1 = *(float4*)(p + 4);
    float4 v2 = *(float4*)(p + 8);

    float mx = fmaxf(fmaxf(fmaxf(v0.x, v0.y), fmaxf(v0.z, v0.w)),
               fmaxf(fmaxf(fmaxf(v1.x, v1.y), fmaxf(v1.z, v1.w)),
                     fmaxf(fmaxf(fmaxf(v2.x, v2.y), fmaxf(v2.z, v2.w)), -1e30f)));
#pragma unroll
    for (int o = 16; o > 0; o >>= 1)
        mx = fmaxf(mx, __shfl_xor_sync(0xffffffffu, mx, o));

    v0.x = expf(v0.x - mx); v0.y = expf(v0.y - mx);
    v0.z = expf(v0.z - mx); v0.w = expf(v0.w - mx);
    v1.x = expf(v1.x - mx); v1.y = expf(v1.y - mx);
    v1.z = expf(v1.z - mx); v1.w = expf(v1.w - mx);
    v2.x = expf(v2.x - mx); v2.y = expf(v2.y - mx);
    v2.z = expf(v2.z - mx); v2.w = expf(v2.w - mx);

    float sum = (v0.x + v0.y + v0.z + v0.w)
              + (v1.x + v1.y + v1.z + v1.w)
              + (v2.x + v2.y + v2.z + v2.w);
#pragma unroll
    for (int o = 16; o > 0; o >>= 1)
        sum += __shfl_xor_sync(0xffffffffu, sum, o);

    float inv = 1.0f / sum;
    v0.x *= inv; v0.y *= inv; v0.z *= inv; v0.w *= inv;
    v1.x *= inv; v1.y *= inv; v1.z *= inv; v1.w *= inv;
    v2.x *= inv; v2.y *= inv; v2.z *= inv; v2.w *= inv;

    *(float4*)(p)     = v0;
    *(float4*)(p + 4) = v1;
    *(float4*)(p + 8) = v2;
}

// ---------------------------------------------------------------------------
extern "C" void kernel_launch(void* const* d_in, const int* in_sizes, int n_in,
                              void* d_out, int out_size)
{
    const float* z  = (const float*)d_in[0];
    const float* Wq = (const float*)d_in[1];
    const float* bq = (const float*)d_in[2];
    const float* Wk = (const float*)d_in[3];
    const float* bk = (const float*)d_in[4];
    const float* Wv = (const float*)d_in[5];
    const float* bv = (const float*)d_in[6];
    float* out = (float*)d_out;

    float *Qp, *Kp, *Vp, *Sp;
    cudaGetSymbolAddress((void**)&Qp, g_Q);
    cudaGetSymbolAddress((void**)&Kp, g_K);
    cudaGetSymbolAddress((void**)&Vp, g_V);
    cudaGetSymbolAddress((void**)&Sp, g_S);

    cudaFuncSetAttribute(mma_gemm<0>, cudaFuncAttributeMaxDynamicSharedMemorySize, SMEM_BYTES);
    cudaFuncSetAttribute(mma_gemm<1>, cudaFuncAttributeMaxDynamicSharedMemorySize, SMEM_BYTES);
    cudaFuncSetAttribute(mma_gemm<2>, cudaFuncAttributeMaxDynamicSharedMemorySize, SMEM_BYTES);

    dim3 blk(NTH);

    // Stage 1: Q/K/V projections. bx = w*3 + ntile (9), by = mtile (768)
    mma_gemm<0><<<dim3(9, 768), blk, SMEM_BYTES>>>(
        z, Wq, Wk, Wv, bq, bk, bv, Qp, Kp, Vp);

    // Stage 2: masked scaled scores
    mma_gemm<1><<<dim3(3, 3, 256), blk, SMEM_BYTES>>>(
        Qp, Kp, nullptr, nullptr, nullptr, nullptr, nullptr,
        Sp, nullptr, nullptr);

    // Softmax in place
    softmax_kernel<<<(256 * 384) / 8, blk>>>(Sp);

    // Stage 3: out = P @ V (K-loop truncated per causal structure)
    mma_gemm<2><<<dim3(3, 3, 256), blk, SMEM_BYTES>>>(
        Sp, Vp, nullptr, nullptr, nullptr, nullptr, nullptr,
        out, nullptr, nullptr);
}

// round 4
// speedup vs baseline: 2.5304x; 1.0079x over previous
#include <cuda_runtime.h>
#include <cuda_bf16.h>
#include <math.h>
#include <stdint.h>

#define NTH 256
#define ROWP 192                 // uint32 pairs per 384-row
#define BP 73728                 // pairs per batch (384*192)
#define BSTRIDE 147456           // floats per batch (384*384)
static const float INV_SQRT_D = 0.05103103630798288f;

#define NPAIR 18874368           // 256*384*384/2

// split bf16 hi/lo operand arrays (packed as bf16x2 k-pairs)
__device__ uint32_t g_zh[NPAIR],  g_zl[NPAIR];
__device__ uint32_t g_Wh[3 * 73728], g_Wl[3 * 73728];
__device__ uint32_t g_Qh[NPAIR],  g_Ql[NPAIR];
__device__ uint32_t g_Kh[NPAIR],  g_Kl[NPAIR];
__device__ uint32_t g_Vth[NPAIR], g_Vtl[NPAIR];   // transposed: [b][d][token]
__device__ uint32_t g_Ph[NPAIR],  g_Pl[NPAIR];
__device__ float    g_S[37748736];

// smem: mainloop 64KB (A_HI/A_LO/B_HI/B_LO, 2 bufs x 8KB each region);
// V-transpose staging reuses as float[128][132]
#define A_HI 0
#define A_LO 16384
#define B_HI 32768
#define B_LO 49152
#define SMEM_BYTES 69632

#define MMA(d, a, b) \
    asm volatile("mma.sync.aligned.m16n8k16.row.col.f32.bf16.bf16.f32 " \
        "{%0,%1,%2,%3},{%4,%5,%6,%7},{%8,%9},{%0,%1,%2,%3};" \
        : "+f"((d)[0]), "+f"((d)[1]), "+f"((d)[2]), "+f"((d)[3]) \
        : "r"((a).x), "r"((a).y), "r"((a).z), "r"((a).w), \
          "r"((b).x), "r"((b).y))

__device__ __forceinline__ void splitpack(float x, float y,
                                          uint32_t& hi, uint32_t& lo) {
    __nv_bfloat16 hx = __float2bfloat16(x);
    __nv_bfloat16 hy = __float2bfloat16(y);
    float lx = x - __bfloat162float(hx);
    float ly = y - __bfloat162float(hy);
    __nv_bfloat162 h2 = __halves2bfloat162(hx, hy);
    __nv_bfloat162 l2 = __floats2bfloat162_rn(lx, ly);
    hi = reinterpret_cast<uint32_t&>(h2);
    lo = reinterpret_cast<uint32_t&>(l2);
}

// ---------------- pre-split kernels ----------------
__global__ __launch_bounds__(256) void presplit_z(const float* __restrict__ z) {
    size_t i = (size_t)blockIdx.x * 256 + threadIdx.x;   // < NPAIR
    float2 v = ((const float2*)z)[i];
    splitpack(v.x, v.y, g_zh[i], g_zl[i]);
}
__global__ __launch_bounds__(256) void presplit_w(const float* __restrict__ Wq,
                                                  const float* __restrict__ Wk,
                                                  const float* __restrict__ Wv) {
    int i = blockIdx.x * 256 + threadIdx.x;              // < 3*73728
    int w = i / 73728, p = i % 73728;
    const float* W = (w == 0) ? Wq : (w == 1) ? Wk : Wv;
    float2 v = ((const float2*)W)[p];
    splitpack(v.x, v.y, g_Wh[i], g_Wl[i]);
}

// ---------------------------------------------------------------------------
// Unified tensor-core GEMM (128x128 tile, KC=32, split-bf16 3-term).
// MODE 0: QKV projection. grid(9, 768)
// MODE 1: scores (lower-triangle tiles only). grid(6, 256)
// MODE 2: out = P @ V. grid(3, 3, 256)
// ---------------------------------------------------------------------------
template <int MODE>
__global__ __launch_bounds__(NTH, 1) void gemm(
    const float* __restrict__ bq, const float* __restrict__ bk,
    const float* __restrict__ bv, float* __restrict__ outp)
{
    extern __shared__ __align__(16) char sm[];
    const int tid = threadIdx.x;
    const int lane = tid & 31;
    const int wid = tid >> 5;
    const int wm = wid >> 2;
    const int wn = wid & 3;

    const uint32_t *Ah, *Al, *Bh, *Bl;
    const float* bias = nullptr;
    int m0, n0, NKT, w = 0, mt = 0, b = 0;

    if (MODE == 0) {
        w = blockIdx.x / 3;
        int nt = blockIdx.x % 3;
        m0 = blockIdx.y * 128; n0 = nt * 128;
        Ah = g_zh; Al = g_zl;
        Bh = g_Wh + w * 73728; Bl = g_Wl + w * 73728;
        bias = (w == 0) ? bq : (w == 1) ? bk : bv;
        NKT = 12;
    } else if (MODE == 1) {
        const int mtab[6] = {0, 1, 1, 2, 2, 2};
        const int ntab[6] = {0, 0, 1, 0, 1, 2};
        mt = mtab[blockIdx.x];
        int nt = ntab[blockIdx.x];
        b = blockIdx.y;
        m0 = mt * 128; n0 = nt * 128;
        Ah = g_Qh + (size_t)b * BP; Al = g_Ql + (size_t)b * BP;
        Bh = g_Kh + (size_t)b * BP; Bl = g_Kl + (size_t)b * BP;
        NKT = 12;
    } else {
        int nt = blockIdx.x; mt = blockIdx.y; b = blockIdx.z;
        m0 = mt * 128; n0 = nt * 128;
        Ah = g_Ph + (size_t)b * BP;  Al = g_Pl + (size_t)b * BP;
        Bh = g_Vth + (size_t)b * BP; Bl = g_Vtl + (size_t)b * BP;
        NKT = (mt + 1) * 4;
    }

    // ---- fragment-order loader indices (same mapping as validated R3) ----
    const int abase = tid >> 4;   // 0..15 row base
    const int akp   = tid & 15;   // k-pair within 32-chunk
    const int aslab = akp >> 3;
    const int alane = (abase & 7) * 4 + (akp & 3);
    const int areg  = ((akp >> 2) & 1) * 2 + ((abase >> 3) & 1);
    const int offA0 = aslab * 4096 + alane * 16 + areg * 4;
    const int breg  = (akp >> 2) & 1;
    const int offB0 = aslab * 4096 + (abase >> 3) * 256 + alane * 8 + breg * 4;

    const uint32_t* pAh = Ah + (size_t)(m0 + abase) * ROWP + akp;
    const uint32_t* pAl = Al + (size_t)(m0 + abase) * ROWP + akp;
    const uint32_t* pBh = Bh + (size_t)(n0 + abase) * ROWP + akp;
    const uint32_t* pBl = Bl + (size_t)(n0 + abase) * ROWP + akp;

    uint32_t pah[8], pal[8], pbh[8], pbl[8];

    // prefetch kt=0
#pragma unroll
    for (int i = 0; i < 8; i++) {
        pah[i] = pAh[i * 3072]; pal[i] = pAl[i * 3072];
        pbh[i] = pBh[i * 3072]; pbl[i] = pBl[i * 3072];
    }
    // store kt=0 into buf 0
#pragma unroll
    for (int i = 0; i < 8; i++) {
        *(uint32_t*)(sm + A_HI + offA0 + i * 512) = pah[i];
        *(uint32_t*)(sm + A_LO + offA0 + i * 512) = pal[i];
        *(uint32_t*)(sm + B_HI + offB0 + i * 512) = pbh[i];
        *(uint32_t*)(sm + B_LO + offB0 + i * 512) = pbl[i];
    }
    __syncthreads();

    float acc[4][4][4];
#pragma unroll
    for (int i = 0; i < 4; i++)
#pragma unroll
        for (int j = 0; j < 4; j++)
#pragma unroll
            for (int r = 0; r < 4; r++) acc[i][j][r] = 0.0f;

    for (int kt = 0; kt < NKT; kt++) {
        const int buf = kt & 1;
        const bool more = (kt + 1) < NKT;
        if (more) {
            const int ko = (kt + 1) * 16;
#pragma unroll
            for (int i = 0; i < 8; i++) {
                pah[i] = pAh[ko + i * 3072]; pal[i] = pAl[ko + i * 3072];
                pbh[i] = pBh[ko + i * 3072]; pbl[i] = pBl[ko + i * 3072];
            }
        }

        {
            char* base = sm + buf * 8192;
#pragma unroll
            for (int s = 0; s < 2; s++) {
                uint4 ah[4], al[4];
                uint2 bh[4], bl[4];
#pragma unroll
                for (int i = 0; i < 4; i++) {
                    int off = s * 4096 + (wm * 4 + i) * 512 + lane * 16;
                    ah[i] = *(const uint4*)(base + A_HI + off);
                    al[i] = *(const uint4*)(base + A_LO + off);
                }
#pragma unroll
                for (int j = 0; j < 4; j++) {
                    int off = s * 4096 + (wn * 4 + j) * 256 + lane * 8;
                    bh[j] = *(const uint2*)(base + B_HI + off);
                    bl[j] = *(const uint2*)(base + B_LO + off);
                }
#pragma unroll
                for (int i = 0; i < 4; i++)
#pragma unroll
                    for (int j = 0; j < 4; j++) {
                        MMA(acc[i][j], ah[i], bh[j]);
                        MMA(acc[i][j], ah[i], bl[j]);
                        MMA(acc[i][j], al[i], bh[j]);
                    }
            }
        }

        if (more) {
            char* dst = sm + (buf ^ 1) * 8192;
#pragma unroll
            for (int i = 0; i < 8; i++) {
                *(uint32_t*)(dst + A_HI + offA0 + i * 512) = pah[i];
                *(uint32_t*)(dst + A_LO + offA0 + i * 512) = pal[i];
                *(uint32_t*)(dst + B_HI + offB0 + i * 512) = pbh[i];
                *(uint32_t*)(dst + B_LO + offB0 + i * 512) = pbl[i];
            }
        }
        __syncthreads();
    }

    // ---- epilogues ----
    const int g = lane >> 2, t = lane & 3;

    if (MODE == 0 && w < 2) {
        uint32_t* Oh = (w == 0) ? g_Qh : g_Kh;
        uint32_t* Ol = (w == 0) ? g_Ql : g_Kl;
#pragma unroll
        for (int i = 0; i < 4; i++) {
            const int r0 = m0 + wm * 64 + i * 16 + g;
#pragma unroll
            for (int j = 0; j < 4; j++) {
                const int c0 = n0 + wn * 32 + j * 8 + t * 2;
                float b0 = bias[c0], b1 = bias[c0 + 1];
                uint32_t h0, l0, h1, l1;
                splitpack(acc[i][j][0] + b0, acc[i][j][1] + b1, h0, l0);
                splitpack(acc[i][j][2] + b0, acc[i][j][3] + b1, h1, l1);
                size_t p0 = (size_t)r0 * ROWP + (c0 >> 1);
                Oh[p0] = h0; Ol[p0] = l0;
                Oh[p0 + 8 * ROWP] = h1; Ol[p0 + 8 * ROWP] = l1;
            }
        }
    } else if (MODE == 0) {
        // V: stage fp32 tile in smem, then transposed split write to Vt
        float* s = (float*)sm;   // [128][132]
#pragma unroll
        for (int i = 0; i < 4; i++) {
            const int rl = wm * 64 + i * 16 + g;
#pragma unroll
            for (int j = 0; j < 4; j++) {
                const int c = wn * 32 + j * 8 + t * 2;
                float b0 = bias[n0 + c], b1 = bias[n0 + c + 1];
                s[rl * 132 + c]           = acc[i][j][0] + b0;
                s[rl * 132 + c + 1]       = acc[i][j][1] + b1;
                s[(rl + 8) * 132 + c]     = acc[i][j][2] + b0;
                s[(rl + 8) * 132 + c + 1] = acc[i][j][3] + b1;
            }
        }
        __syncthreads();
        const int bb = m0 / 384;
        const int l0tok = m0 % 384;
#pragma unroll
        for (int it = 0; it < 8; it++) {
            int idx = it * 256 + tid;        // 0..2047
            int dl = idx & 127;
            int tb = (idx >> 7) * 8;         // token block
            float v[8];
#pragma unroll
            for (int u = 0; u < 8; u++) v[u] = s[(tb + u) * 132 + dl];
            uint32_t hh[4], ll[4];
#pragma unroll
            for (int p = 0; p < 4; p++) splitpack(v[2 * p], v[2 * p + 1], hh[p], ll[p]);
            size_t base = (size_t)bb * BP + (size_t)(n0 + dl) * ROWP +
                          ((l0tok + tb) >> 1);
            *(uint4*)&g_Vth[base] = make_uint4(hh[0], hh[1], hh[2], hh[3]);
            *(uint4*)&g_Vtl[base] = make_uint4(ll[0], ll[1], ll[2], ll[3]);
        }
    } else if (MODE == 1) {
        float* So = g_S + (size_t)b * BSTRIDE;
#pragma unroll
        for (int i = 0; i < 4; i++) {
            const int r0 = m0 + wm * 64 + i * 16 + g;
#pragma unroll
            for (int j = 0; j < 4; j++) {
                const int c0 = n0 + wn * 32 + j * 8 + t * 2;
                float2 v0 = make_float2(acc[i][j][0] * INV_SQRT_D,
                                        acc[i][j][1] * INV_SQRT_D);
                float2 v1 = make_float2(acc[i][j][2] * INV_SQRT_D,
                                        acc[i][j][3] * INV_SQRT_D);
                *(float2*)&So[(size_t)r0 * 384 + c0] = v0;
                *(float2*)&So[(size_t)(r0 + 8) * 384 + c0] = v1;
            }
        }
    } else {
        float* Oo = outp + (size_t)b * BSTRIDE;
#pragma unroll
        for (int i = 0; i < 4; i++) {
            const int r0 = m0 + wm * 64 + i * 16 + g;
#pragma unroll
            for (int j = 0; j < 4; j++) {
                const int c0 = n0 + wn * 32 + j * 8 + t * 2;
                *(float2*)&Oo[(size_t)r0 * 384 + c0] =
                    make_float2(acc[i][j][0], acc[i][j][1]);
                *(float2*)&Oo[(size_t)(r0 + 8) * 384 + c0] =
                    make_float2(acc[i][j][2], acc[i][j][3]);
            }
        }
    }
}

// ---------------------------------------------------------------------------
// Softmax: warp per row; index-based causal mask; writes split-bf16 P.
// ---------------------------------------------------------------------------
__global__ __launch_bounds__(256) void softmax_kernel()
{
    const int row = blockIdx.x * 8 + (threadIdx.x >> 5);   // global q-row
    const int lane = threadIdx.x & 31;
    const int q = row % 384;
    const float* p = g_S + (size_t)row * 384 + lane * 12;

    float v[12];
    *(float4*)&v[0] = *(const float4*)(p);
    *(float4*)&v[4] = *(const float4*)(p + 4);
    *(float4*)&v[8] = *(const float4*)(p + 8);

    const int kb = lane * 12;
#pragma unroll
    for (int j = 0; j < 12; j++)
        if (kb + j > q) v[j] = -1e30f;

    float mx = -1e30f;
#pragma unroll
    for (int j = 0; j < 12; j++) mx = fmaxf(mx, v[j]);
#pragma unroll
    for (int o = 16; o > 0; o >>= 1)
        mx = fmaxf(mx, __shfl_xor_sync(0xffffffffu, mx, o));

    float sum = 0.0f;
#pragma unroll
    for (int j = 0; j < 12; j++) { v[j] = expf(v[j] - mx); sum += v[j]; }
#pragma unroll
    for (int o = 16; o > 0; o >>= 1)
        sum += __shfl_xor_sync(0xffffffffu, sum, o);

    float inv = 1.0f / sum;
    size_t base = (size_t)row * ROWP + lane * 6;
#pragma unroll
    for (int pp = 0; pp < 6; pp++) {
        uint32_t h, l;
        splitpack(v[2 * pp] * inv, v[2 * pp + 1] * inv, h, l);
        g_Ph[base + pp] = h;
        g_Pl[base + pp] = l;
    }
}

// ---------------------------------------------------------------------------
extern "C" void kernel_launch(void* const* d_in, const int* in_sizes, int n_in,
                              void* d_out, int out_size)
{
    const float* z  = (const float*)d_in[0];
    const float* Wq = (const float*)d_in[1];
    const float* bq = (const float*)d_in[2];
    const float* Wk = (const float*)d_in[3];
    const float* bk = (const float*)d_in[4];
    const float* Wv = (const float*)d_in[5];
    const float* bv = (const float*)d_in[6];
    float* out = (float*)d_out;

    cudaFuncSetAttribute(gemm<0>, cudaFuncAttributeMaxDynamicSharedMemorySize, SMEM_BYTES);
    cudaFuncSetAttribute(gemm<1>, cudaFuncAttributeMaxDynamicSharedMemorySize, SMEM_BYTES);
    cudaFuncSetAttribute(gemm<2>, cudaFuncAttributeMaxDynamicSharedMemorySize, SMEM_BYTES);

    dim3 blk(NTH);

    presplit_z<<<NPAIR / 256, blk>>>(z);
    presplit_w<<<(3 * 73728) / 256, blk>>>(Wq, Wk, Wv);

    // Stage 1: Q/K/V projections (bx = w*3+nt, by = mtile)
    gemm<0><<<dim3(9, 768), blk, SMEM_BYTES>>>(bq, bk, bv, nullptr);

    // Stage 2: scores, lower-triangle tiles only
    gemm<1><<<dim3(6, 256), blk, SMEM_BYTES>>>(nullptr, nullptr, nullptr, nullptr);

    // Softmax (index-masked) -> split-bf16 P
    softmax_kernel<<<(256 * 384) / 8, blk>>>();

    // Stage 3: out = P @ V (K truncated by causal structure)
    gemm<2><<<dim3(3, 3, 256), blk, SMEM_BYTES>>>(nullptr, nullptr, nullptr, out);
}

// round 5
// speedup vs baseline: 2.7785x; 1.0980x over previous
#include <cuda_runtime.h>
#include <cuda_bf16.h>
#include <stdint.h>

#define NTH 256
#define BSTRIDE 147456               // floats per batch (384*384)
static const float INV_SQRT_D = 0.05103103630798288f;

#define NPAIR 18874368               // 256*384*192
#define TILE_U32 2048                // uint32 per 128x32 fragment tile (8KB)

// All operands stored as fragment-ordered 128x32 tiles: [row_tile][kt][2048]
__device__ uint32_t g_zh[NPAIR],  g_zl[NPAIR];
__device__ uint32_t g_Wh[3 * 36 * TILE_U32], g_Wl[3 * 36 * TILE_U32];
__device__ uint32_t g_Qh[NPAIR],  g_Ql[NPAIR];
__device__ uint32_t g_Kh[NPAIR],  g_Kl[NPAIR];
__device__ uint32_t g_Vth[NPAIR], g_Vtl[NPAIR];   // [b][d-tile][token-kt]
__device__ uint32_t g_Ph[NPAIR],  g_Pl[NPAIR];
__device__ float    g_S[37748736];

#define NSTAGE 4
#define STAGE_BYTES 32768            // A_HI 8K | A_LO 8K | B_HI 8K | B_LO 8K
#define SMEM_BYTES (NSTAGE * STAGE_BYTES)

// fragment-order byte offset of (row r 0..127, k-pair p 0..15) in an 8KB tile
__device__ __forceinline__ int offA(int r, int p) {
    return ((p >> 3) << 12) + ((r >> 4) << 9) +
           (((r & 7) * 4 + (p & 3)) << 4) +
           (((p >> 2) & 1) << 3) + (((r >> 3) & 1) << 2);
}
__device__ __forceinline__ int offB(int n, int p) {
    return ((p >> 3) << 12) + ((n >> 3) << 8) +
           (((n & 7) * 4 + (p & 3)) << 3) + (((p >> 2) & 1) << 2);
}

#define MMA(d, a, b) \
    asm volatile("mma.sync.aligned.m16n8k16.row.col.f32.bf16.bf16.f32 " \
        "{%0,%1,%2,%3},{%4,%5,%6,%7},{%8,%9},{%0,%1,%2,%3};" \
        : "+f"((d)[0]), "+f"((d)[1]), "+f"((d)[2]), "+f"((d)[3]) \
        : "r"((a).x), "r"((a).y), "r"((a).z), "r"((a).w), \
          "r"((b).x), "r"((b).y))

#define CP16(sa, gp) \
    asm volatile("cp.async.cg.shared.global [%0], [%1], 16;" :: "r"(sa), "l"(gp))
#define CP_COMMIT() asm volatile("cp.async.commit_group;" ::: "memory")
#define CP_WAIT2()  asm volatile("cp.async.wait_group 2;" ::: "memory")

__device__ __forceinline__ uint32_t smem_u32(const void* p) {
    uint32_t a;
    asm("{ .reg .u64 t; cvta.to.shared.u64 t, %1; cvt.u32.u64 %0, t; }"
        : "=r"(a) : "l"(p));
    return a;
}

__device__ __forceinline__ void splitpack(float x, float y,
                                          uint32_t& hi, uint32_t& lo) {
    __nv_bfloat16 hx = __float2bfloat16(x);
    __nv_bfloat16 hy = __float2bfloat16(y);
    float lx = x - __bfloat162float(hx);
    float ly = y - __bfloat162float(hy);
    __nv_bfloat162 h2 = __halves2bfloat162(hx, hy);
    __nv_bfloat162 l2 = __floats2bfloat162_rn(lx, ly);
    hi = reinterpret_cast<uint32_t&>(h2);
    lo = reinterpret_cast<uint32_t&>(l2);
}

// ---------------- pre-split into fragment tiles ----------------
__global__ __launch_bounds__(256) void presplit_z(const float* __restrict__ z) {
    int idx = blockIdx.x * 256 + threadIdx.x;            // < NPAIR
    int rg = idx / 192, kp = idx % 192;
    float2 v = *(const float2*)&z[(size_t)rg * 384 + kp * 2];
    uint32_t h, l; splitpack(v.x, v.y, h, l);
    size_t o = (size_t)((rg >> 7) * 12 + (kp >> 4)) * TILE_U32 +
               (offA(rg & 127, kp & 15) >> 2);
    g_zh[o] = h; g_zl[o] = l;
}
__global__ __launch_bounds__(256) void presplit_w(const float* __restrict__ Wq,
                                                  const float* __restrict__ Wk,
                                                  const float* __restrict__ Wv) {
    int idx = blockIdx.x * 256 + threadIdx.x;            // < 3*73728
    int w = idx / 73728, rem = idx % 73728;
    int ng = rem / 192, kp = rem % 192;
    const float* W = (w == 0) ? Wq : (w == 1) ? Wk : Wv;
    float2 v = *(const float2*)&W[(size_t)ng * 384 + kp * 2];
    uint32_t h, l; splitpack(v.x, v.y, h, l);
    size_t o = (size_t)(w * 36 + (ng >> 7) * 12 + (kp >> 4)) * TILE_U32 +
               (offB(ng & 127, kp & 15) >> 2);
    g_Wh[o] = h; g_Wl[o] = l;
}

// ---------------------------------------------------------------------------
// Unified multistage tensor-core GEMM (128x128 tile, KC=32, split-bf16 3-term)
// MODE 0: QKV projection grid(9,768) | MODE 1: scores grid(6,256)
// MODE 2: out = P @ V grid(3,3,256)
// ---------------------------------------------------------------------------
template <int MODE>
__global__ __launch_bounds__(NTH, 1) void gemm(
    const float* __restrict__ bq, const float* __restrict__ bk,
    const float* __restrict__ bv, float* __restrict__ outp)
{
    extern __shared__ __align__(16) char sm[];
    const uint32_t smb = smem_u32(sm);
    const int tid = threadIdx.x;
    const int lane = tid & 31;
    const int wid = tid >> 5;
    const int wm = wid >> 2;
    const int wn = wid & 3;

    const uint32_t *Ah, *Al, *Bh, *Bl;
    const float* bias = nullptr;
    int NKT, n0 = 0, m0 = 0, w = 0, mt = 0, b = 0;

    if (MODE == 0) {
        w = blockIdx.x / 3;
        int nt = blockIdx.x % 3;
        n0 = nt * 128;
        Ah = g_zh + (size_t)blockIdx.y * 24576;
        Al = g_zl + (size_t)blockIdx.y * 24576;
        Bh = g_Wh + (size_t)(w * 36 + nt * 12) * TILE_U32;
        Bl = g_Wl + (size_t)(w * 36 + nt * 12) * TILE_U32;
        bias = (w == 0) ? bq : (w == 1) ? bk : bv;
        NKT = 12;
    } else if (MODE == 1) {
        const int mtab[6] = {0, 1, 1, 2, 2, 2};
        const int ntab[6] = {0, 0, 1, 0, 1, 2};
        mt = mtab[blockIdx.x];
        int nt = ntab[blockIdx.x];
        b = blockIdx.y;
        m0 = mt * 128; n0 = nt * 128;
        Ah = g_Qh + (size_t)(b * 3 + mt) * 24576;
        Al = g_Ql + (size_t)(b * 3 + mt) * 24576;
        Bh = g_Kh + (size_t)(b * 3 + nt) * 24576;
        Bl = g_Kl + (size_t)(b * 3 + nt) * 24576;
        NKT = 12;
    } else {
        int nt = blockIdx.x; mt = blockIdx.y; b = blockIdx.z;
        m0 = mt * 128; n0 = nt * 128;
        Ah = g_Ph + (size_t)(b * 3 + mt) * 24576;
        Al = g_Pl + (size_t)(b * 3 + mt) * 24576;
        Bh = g_Vth + (size_t)(b * 3 + nt) * 24576;
        Bl = g_Vtl + (size_t)(b * 3 + nt) * 24576;
        NKT = (mt + 1) * 4;
    }

    // issue all copies for one kt into one stage (8 x cp.async.cg 16B / thread)
    auto issue = [&](int kt, int st) {
        const uint32_t d0 = smb + st * STAGE_BYTES + tid * 16;
        const int go = kt * TILE_U32 + tid * 4;
        CP16(d0,              Ah + go);  CP16(d0 + 4096,          Ah + go + 1024);
        CP16(d0 + 8192,       Al + go);  CP16(d0 + 8192 + 4096,   Al + go + 1024);
        CP16(d0 + 16384,      Bh + go);  CP16(d0 + 16384 + 4096,  Bh + go + 1024);
        CP16(d0 + 24576,      Bl + go);  CP16(d0 + 24576 + 4096,  Bl + go + 1024);
    };

    issue(0, 0); CP_COMMIT();
    issue(1, 1); CP_COMMIT();
    issue(2, 2); CP_COMMIT();

    float acc[4][4][4];
#pragma unroll
    for (int i = 0; i < 4; i++)
#pragma unroll
        for (int j = 0; j < 4; j++)
#pragma unroll
            for (int r = 0; r < 4; r++) acc[i][j][r] = 0.0f;

    for (int kt = 0; kt < NKT; kt++) {
        CP_WAIT2();
        __syncthreads();
        if (kt + 3 < NKT) issue(kt + 3, (kt + 3) & 3);
        CP_COMMIT();

        const char* base = sm + (kt & 3) * STAGE_BYTES;
#pragma unroll
        for (int s = 0; s < 2; s++) {
            uint4 ah[4], al[4];
            uint2 bh[4], bl[4];
#pragma unroll
            for (int i = 0; i < 4; i++) {
                int off = s * 4096 + (wm * 4 + i) * 512 + lane * 16;
                ah[i] = *(const uint4*)(base + off);
                al[i] = *(const uint4*)(base + 8192 + off);
            }
#pragma unroll
            for (int j = 0; j < 4; j++) {
                int off = s * 4096 + (wn * 4 + j) * 256 + lane * 8;
                bh[j] = *(const uint2*)(base + 16384 + off);
                bl[j] = *(const uint2*)(base + 24576 + off);
            }
#pragma unroll
            for (int i = 0; i < 4; i++)
#pragma unroll
                for (int j = 0; j < 4; j++) {
                    MMA(acc[i][j], ah[i], bh[j]);
                    MMA(acc[i][j], ah[i], bl[j]);
                    MMA(acc[i][j], al[i], bh[j]);
                }
        }
    }

    // ---- epilogues ----
    const int g = lane >> 2, t = lane & 3;

    if (MODE == 0 && w < 2) {
        uint32_t* Oh = (w == 0) ? g_Qh : g_Kh;
        uint32_t* Ol = (w == 0) ? g_Ql : g_Kl;
        const size_t tb0 = (size_t)blockIdx.y * 12;
#pragma unroll
        for (int i = 0; i < 4; i++) {
            const int rl = wm * 64 + i * 16 + g;
#pragma unroll
            for (int j = 0; j < 4; j++) {
                const int c0 = n0 + wn * 32 + j * 8 + t * 2;
                float b0 = bias[c0], b1 = bias[c0 + 1];
                uint32_t h0, l0, h1, l1;
                splitpack(acc[i][j][0] + b0, acc[i][j][1] + b1, h0, l0);
                splitpack(acc[i][j][2] + b0, acc[i][j][3] + b1, h1, l1);
                size_t tile = (tb0 + (c0 >> 5)) * TILE_U32;
                int p = (c0 & 31) >> 1;
                size_t o1, o2;
                if (w == 0) { o1 = tile + (offA(rl, p) >> 2); o2 = tile + (offA(rl + 8, p) >> 2); }
                else        { o1 = tile + (offB(rl, p) >> 2); o2 = tile + (offB(rl + 8, p) >> 2); }
                Oh[o1] = h0; Ol[o1] = l0;
                Oh[o2] = h1; Ol[o2] = l1;
            }
        }
    } else if (MODE == 0) {
        // V: stage fp32 tile in smem, then transposed fragment-tile write
        __syncthreads();
        float* s = (float*)sm;   // [128][132]
#pragma unroll
        for (int i = 0; i < 4; i++) {
            const int rl = wm * 64 + i * 16 + g;
#pragma unroll
            for (int j = 0; j < 4; j++) {
                const int c = wn * 32 + j * 8 + t * 2;
                float b0 = bias[n0 + c], b1 = bias[n0 + c + 1];
                s[rl * 132 + c]           = acc[i][j][0] + b0;
                s[rl * 132 + c + 1]       = acc[i][j][1] + b1;
                s[(rl + 8) * 132 + c]     = acc[i][j][2] + b0;
                s[(rl + 8) * 132 + c + 1] = acc[i][j][3] + b1;
            }
        }
        __syncthreads();
        const int bb = blockIdx.y / 3;
        const int l0tok = (blockIdx.y % 3) * 128;
#pragma unroll
        for (int it = 0; it < 8; it++) {
            int idx = it * 256 + tid;
            int dl = idx & 127;
            int tb = (idx >> 7) * 8;
            float v[8];
#pragma unroll
            for (int u = 0; u < 8; u++) v[u] = s[(tb + u) * 132 + dl];
            int tok0 = l0tok + tb;
            size_t tile = (size_t)((bb * 3 + (n0 >> 7)) * 12 + (tok0 >> 5)) * TILE_U32;
            int p0 = (tok0 & 31) >> 1;
#pragma unroll
            for (int pp = 0; pp < 4; pp++) {
                uint32_t h, l;
                splitpack(v[2 * pp], v[2 * pp + 1], h, l);
                size_t o = tile + (offB(dl, p0 + pp) >> 2);
                g_Vth[o] = h; g_Vtl[o] = l;
            }
        }
    } else if (MODE == 1) {
        float* So = g_S + (size_t)b * BSTRIDE;
#pragma unroll
        for (int i = 0; i < 4; i++) {
            const int r0 = m0 + wm * 64 + i * 16 + g;
#pragma unroll
            for (int j = 0; j < 4; j++) {
                const int c0 = n0 + wn * 32 + j * 8 + t * 2;
                *(float2*)&So[(size_t)r0 * 384 + c0] =
                    make_float2(acc[i][j][0] * INV_SQRT_D, acc[i][j][1] * INV_SQRT_D);
                *(float2*)&So[(size_t)(r0 + 8) * 384 + c0] =
                    make_float2(acc[i][j][2] * INV_SQRT_D, acc[i][j][3] * INV_SQRT_D);
            }
        }
    } else {
        float* Oo = outp + (size_t)b * BSTRIDE;
#pragma unroll
        for (int i = 0; i < 4; i++) {
            const int r0 = m0 + wm * 64 + i * 16 + g;
#pragma unroll
            for (int j = 0; j < 4; j++) {
                const int c0 = n0 + wn * 32 + j * 8 + t * 2;
                *(float2*)&Oo[(size_t)r0 * 384 + c0] =
                    make_float2(acc[i][j][0], acc[i][j][1]);
                *(float2*)&Oo[(size_t)(r0 + 8) * 384 + c0] =
                    make_float2(acc[i][j][2], acc[i][j][3]);
            }
        }
    }
}

// ---------------------------------------------------------------------------
// Softmax: warp/row, index-based causal mask, writes P as fragment tiles.
// ---------------------------------------------------------------------------
__global__ __launch_bounds__(256) void softmax_kernel()
{
    const int row = blockIdx.x * 8 + (threadIdx.x >> 5);   // 0..98303
    const int lane = threadIdx.x & 31;
    const int q = row % 384;
    const float* p = g_S + (size_t)row * 384 + lane * 12;

    float v[12];
    *(float4*)&v[0] = *(const float4*)(p);
    *(float4*)&v[4] = *(const float4*)(p + 4);
    *(float4*)&v[8] = *(const float4*)(p + 8);

    const int kb = lane * 12;
#pragma unroll
    for (int j = 0; j < 12; j++)
        if (kb + j > q) v[j] = -1e30f;

    float mx = -1e30f;
#pragma unroll
    for (int j = 0; j < 12; j++) mx = fmaxf(mx, v[j]);
#pragma unroll
    for (int o = 16; o > 0; o >>= 1)
        mx = fmaxf(mx, __shfl_xor_sync(0xffffffffu, mx, o));

    float sum = 0.0f;
#pragma unroll
    for (int j = 0; j < 12; j++) { v[j] = expf(v[j] - mx); sum += v[j]; }
#pragma unroll
    for (int o = 16; o > 0; o >>= 1)
        sum += __shfl_xor_sync(0xffffffffu, sum, o);

    const float inv = 1.0f / sum;
    const int rl = row & 127;
    const size_t tb0 = (size_t)(row >> 7) * 12;
#pragma unroll
    for (int pp = 0; pp < 6; pp++) {
        int kp = lane * 6 + pp;
        uint32_t h, l;
        splitpack(v[2 * pp] * inv, v[2 * pp + 1] * inv, h, l);
        size_t o = (tb0 + (kp >> 4)) * TILE_U32 + (offA(rl, kp & 15) >> 2);
        g_Ph[o] = h; g_Pl[o] = l;
    }
}

// ---------------------------------------------------------------------------
extern "C" void kernel_launch(void* const* d_in, const int* in_sizes, int n_in,
                              void* d_out, int out_size)
{
    const float* z  = (const float*)d_in[0];
    const float* Wq = (const float*)d_in[1];
    const float* bq = (const float*)d_in[2];
    const float* Wk = (const float*)d_in[3];
    const float* bk = (const float*)d_in[4];
    const float* Wv = (const float*)d_in[5];
    const float* bv = (const float*)d_in[6];
    float* out = (float*)d_out;

    cudaFuncSetAttribute(gemm<0>, cudaFuncAttributeMaxDynamicSharedMemorySize, SMEM_BYTES);
    cudaFuncSetAttribute(gemm<1>, cudaFuncAttributeMaxDynamicSharedMemorySize, SMEM_BYTES);
    cudaFuncSetAttribute(gemm<2>, cudaFuncAttributeMaxDynamicSharedMemorySize, SMEM_BYTES);

    dim3 blk(NTH);

    presplit_z<<<NPAIR / 256, blk>>>(z);
    presplit_w<<<(3 * 73728) / 256, blk>>>(Wq, Wk, Wv);

    gemm<0><<<dim3(9, 768), blk, SMEM_BYTES>>>(bq, bk, bv, nullptr);
    gemm<1><<<dim3(6, 256), blk, SMEM_BYTES>>>(nullptr, nullptr, nullptr, nullptr);
    softmax_kernel<<<(256 * 384) / 8, blk>>>();
    gemm<2><<<dim3(3, 3, 256), blk, SMEM_BYTES>>>(nullptr, nullptr, nullptr, out);
}

// round 6
// speedup vs baseline: 3.2326x; 1.1634x over previous
#include <cuda_runtime.h>
#include <cuda_bf16.h>
#include <stdint.h>

#define NTH 256
#define BSTRIDE 147456               // floats per batch (384*384)
static const float INV_SQRT_D = 0.05103103630798288f;

#define NPAIR 18874368               // 256*384*192
#define TILE_U32 2048                // uint32 per 128x32 fragment tile (8KB)

// All operands stored as fragment-ordered 128x32 tiles: [row_tile][kt][2048]
__device__ uint32_t g_zh[NPAIR],  g_zl[NPAIR];
__device__ uint32_t g_Wh[3 * 36 * TILE_U32], g_Wl[3 * 36 * TILE_U32];
__device__ uint32_t g_Qh[NPAIR],  g_Ql[NPAIR];
__device__ uint32_t g_Kh[NPAIR],  g_Kl[NPAIR];
__device__ uint32_t g_Vth[NPAIR], g_Vtl[NPAIR];   // [b][d-tile][token-kt]
__device__ uint32_t g_Ph[NPAIR],  g_Pl[NPAIR];
__device__ float    g_S[37748736];

#define NSTAGE 3
#define STAGE_BYTES 32768            // A_HI 8K | A_LO 8K | B_HI 8K | B_LO 8K
#define SMEM_BYTES (NSTAGE * STAGE_BYTES)   // 96KB -> 2 CTAs/SM

// fragment-order byte offset of (row r 0..127, k-pair p 0..15) in an 8KB tile
__device__ __forceinline__ int offA(int r, int p) {
    return ((p >> 3) << 12) + ((r >> 4) << 9) +
           (((r & 7) * 4 + (p & 3)) << 4) +
           (((p >> 2) & 1) << 3) + (((r >> 3) & 1) << 2);
}
__device__ __forceinline__ int offB(int n, int p) {
    return ((p >> 3) << 12) + ((n >> 3) << 8) +
           (((n & 7) * 4 + (p & 3)) << 3) + (((p >> 2) & 1) << 2);
}

#define MMA(d, a, b) \
    asm volatile("mma.sync.aligned.m16n8k16.row.col.f32.bf16.bf16.f32 " \
        "{%0,%1,%2,%3},{%4,%5,%6,%7},{%8,%9},{%0,%1,%2,%3};" \
        : "+f"((d)[0]), "+f"((d)[1]), "+f"((d)[2]), "+f"((d)[3]) \
        : "r"((a).x), "r"((a).y), "r"((a).z), "r"((a).w), \
          "r"((b).x), "r"((b).y))

#define CP16(sa, gp) \
    asm volatile("cp.async.cg.shared.global [%0], [%1], 16;" :: "r"(sa), "l"(gp))
#define CP_COMMIT() asm volatile("cp.async.commit_group;" ::: "memory")
#define CP_WAIT1()  asm volatile("cp.async.wait_group 1;" ::: "memory")

__device__ __forceinline__ uint32_t smem_u32(const void* p) {
    uint32_t a;
    asm("{ .reg .u64 t; cvta.to.shared.u64 t, %1; cvt.u32.u64 %0, t; }"
        : "=r"(a) : "l"(p));
    return a;
}

__device__ __forceinline__ void splitpack(float x, float y,
                                          uint32_t& hi, uint32_t& lo) {
    __nv_bfloat16 hx = __float2bfloat16(x);
    __nv_bfloat16 hy = __float2bfloat16(y);
    float lx = x - __bfloat162float(hx);
    float ly = y - __bfloat162float(hy);
    __nv_bfloat162 h2 = __halves2bfloat162(hx, hy);
    __nv_bfloat162 l2 = __floats2bfloat162_rn(lx, ly);
    hi = reinterpret_cast<uint32_t&>(h2);
    lo = reinterpret_cast<uint32_t&>(l2);
}

// ---------------- pre-split into fragment tiles ----------------
__global__ __launch_bounds__(256) void presplit_z(const float* __restrict__ z) {
    int idx = blockIdx.x * 256 + threadIdx.x;            // < NPAIR
    int rg = idx / 192, kp = idx % 192;
    float2 v = *(const float2*)&z[(size_t)rg * 384 + kp * 2];
    uint32_t h, l; splitpack(v.x, v.y, h, l);
    size_t o = (size_t)((rg >> 7) * 12 + (kp >> 4)) * TILE_U32 +
               (offA(rg & 127, kp & 15) >> 2);
    g_zh[o] = h; g_zl[o] = l;
}
__global__ __launch_bounds__(256) void presplit_w(const float* __restrict__ Wq,
                                                  const float* __restrict__ Wk,
                                                  const float* __restrict__ Wv) {
    int idx = blockIdx.x * 256 + threadIdx.x;            // < 3*73728
    int w = idx / 73728, rem = idx % 73728;
    int ng = rem / 192, kp = rem % 192;
    const float* W = (w == 0) ? Wq : (w == 1) ? Wk : Wv;
    float2 v = *(const float2*)&W[(size_t)ng * 384 + kp * 2];
    uint32_t h, l; splitpack(v.x, v.y, h, l);
    size_t o = (size_t)(w * 36 + (ng >> 7) * 12 + (kp >> 4)) * TILE_U32 +
               (offB(ng & 127, kp & 15) >> 2);
    g_Wh[o] = h; g_Wl[o] = l;
}

// ---------------------------------------------------------------------------
// Unified 3-stage tensor-core GEMM (128x128 tile, KC=32, split-bf16 3-term)
// MODE 0: QKV projection grid(9,768) | MODE 1: scores grid(6,256)
// MODE 2: out = P @ V grid(3,3,256)
// ---------------------------------------------------------------------------
template <int MODE>
__global__ __launch_bounds__(NTH, 2) void gemm(
    const float* __restrict__ bq, const float* __restrict__ bk,
    const float* __restrict__ bv, float* __restrict__ outp)
{
    extern __shared__ __align__(16) char sm[];
    const uint32_t smb = smem_u32(sm);
    const int tid = threadIdx.x;
    const int lane = tid & 31;
    const int wid = tid >> 5;
    const int wm = wid >> 2;
    const int wn = wid & 3;

    const uint32_t *Ah, *Al, *Bh, *Bl;
    const float* bias = nullptr;
    int NKT, n0 = 0, m0 = 0, w = 0, mt = 0, b = 0;

    if (MODE == 0) {
        w = blockIdx.x / 3;
        int nt = blockIdx.x % 3;
        n0 = nt * 128;
        Ah = g_zh + (size_t)blockIdx.y * 24576;
        Al = g_zl + (size_t)blockIdx.y * 24576;
        Bh = g_Wh + (size_t)(w * 36 + nt * 12) * TILE_U32;
        Bl = g_Wl + (size_t)(w * 36 + nt * 12) * TILE_U32;
        bias = (w == 0) ? bq : (w == 1) ? bk : bv;
        NKT = 12;
    } else if (MODE == 1) {
        const int mtab[6] = {0, 1, 1, 2, 2, 2};
        const int ntab[6] = {0, 0, 1, 0, 1, 2};
        mt = mtab[blockIdx.x];
        int nt = ntab[blockIdx.x];
        b = blockIdx.y;
        m0 = mt * 128; n0 = nt * 128;
        Ah = g_Qh + (size_t)(b * 3 + mt) * 24576;
        Al = g_Ql + (size_t)(b * 3 + mt) * 24576;
        Bh = g_Kh + (size_t)(b * 3 + nt) * 24576;
        Bl = g_Kl + (size_t)(b * 3 + nt) * 24576;
        NKT = 12;
    } else {
        int nt = blockIdx.x; mt = blockIdx.y; b = blockIdx.z;
        m0 = mt * 128; n0 = nt * 128;
        Ah = g_Ph + (size_t)(b * 3 + mt) * 24576;
        Al = g_Pl + (size_t)(b * 3 + mt) * 24576;
        Bh = g_Vth + (size_t)(b * 3 + nt) * 24576;
        Bl = g_Vtl + (size_t)(b * 3 + nt) * 24576;
        NKT = (mt + 1) * 4;
    }

    // issue all copies for one kt into one stage (8 x cp.async.cg 16B / thread)
    auto issue = [&](int kt, int st) {
        const uint32_t d0 = smb + st * STAGE_BYTES + tid * 16;
        const int go = kt * TILE_U32 + tid * 4;
        CP16(d0,              Ah + go);  CP16(d0 + 4096,          Ah + go + 1024);
        CP16(d0 + 8192,       Al + go);  CP16(d0 + 8192 + 4096,   Al + go + 1024);
        CP16(d0 + 16384,      Bh + go);  CP16(d0 + 16384 + 4096,  Bh + go + 1024);
        CP16(d0 + 24576,      Bl + go);  CP16(d0 + 24576 + 4096,  Bl + go + 1024);
    };

    issue(0, 0); CP_COMMIT();
    issue(1, 1); CP_COMMIT();

    float acc[4][4][4];
#pragma unroll
    for (int i = 0; i < 4; i++)
#pragma unroll
        for (int j = 0; j < 4; j++)
#pragma unroll
            for (int r = 0; r < 4; r++) acc[i][j][r] = 0.0f;

    int cs = 0, is = 2;
    for (int kt = 0; kt < NKT; kt++) {
        CP_WAIT1();
        __syncthreads();
        if (kt + 2 < NKT) issue(kt + 2, is);
        CP_COMMIT();

        const char* base = sm + cs * STAGE_BYTES;
#pragma unroll
        for (int s = 0; s < 2; s++) {
            uint4 ah[4], al[4];
#pragma unroll
            for (int i = 0; i < 4; i++) {
                int off = s * 4096 + (wm * 4 + i) * 512 + lane * 16;
                ah[i] = *(const uint4*)(base + off);
                al[i] = *(const uint4*)(base + 8192 + off);
            }
#pragma unroll
            for (int j = 0; j < 4; j++) {
                int off = s * 4096 + (wn * 4 + j) * 256 + lane * 8;
                uint2 bh = *(const uint2*)(base + 16384 + off);
                uint2 bl = *(const uint2*)(base + 24576 + off);
#pragma unroll
                for (int i = 0; i < 4; i++) {
                    MMA(acc[i][j], ah[i], bh);
                    MMA(acc[i][j], ah[i], bl);
                    MMA(acc[i][j], al[i], bh);
                }
            }
        }
        cs = (cs == 2) ? 0 : cs + 1;
        is = (is == 2) ? 0 : is + 1;
    }

    // ---- epilogues ----
    const int g = lane >> 2, t = lane & 3;

    if (MODE == 0 && w < 2) {
        uint32_t* Oh = (w == 0) ? g_Qh : g_Kh;
        uint32_t* Ol = (w == 0) ? g_Ql : g_Kl;
        const size_t tb0 = (size_t)blockIdx.y * 12;
#pragma unroll
        for (int i = 0; i < 4; i++) {
            const int rl = wm * 64 + i * 16 + g;
#pragma unroll
            for (int j = 0; j < 4; j++) {
                const int c0 = n0 + wn * 32 + j * 8 + t * 2;
                float b0 = bias[c0], b1 = bias[c0 + 1];
                uint32_t h0, l0, h1, l1;
                splitpack(acc[i][j][0] + b0, acc[i][j][1] + b1, h0, l0);
                splitpack(acc[i][j][2] + b0, acc[i][j][3] + b1, h1, l1);
                size_t tile = (tb0 + (c0 >> 5)) * TILE_U32;
                int p = (c0 & 31) >> 1;
                size_t o1, o2;
                if (w == 0) { o1 = tile + (offA(rl, p) >> 2); o2 = tile + (offA(rl + 8, p) >> 2); }
                else        { o1 = tile + (offB(rl, p) >> 2); o2 = tile + (offB(rl + 8, p) >> 2); }
                Oh[o1] = h0; Ol[o1] = l0;
                Oh[o2] = h1; Ol[o2] = l1;
            }
        }
    } else if (MODE == 0) {
        // V: stage fp32 tile in smem, then transposed fragment-tile write
        __syncthreads();
        float* s = (float*)sm;   // [128][132]
#pragma unroll
        for (int i = 0; i < 4; i++) {
            const int rl = wm * 64 + i * 16 + g;
#pragma unroll
            for (int j = 0; j < 4; j++) {
                const int c = wn * 32 + j * 8 + t * 2;
                float b0 = bias[n0 + c], b1 = bias[n0 + c + 1];
                s[rl * 132 + c]           = acc[i][j][0] + b0;
                s[rl * 132 + c + 1]       = acc[i][j][1] + b1;
                s[(rl + 8) * 132 + c]     = acc[i][j][2] + b0;
                s[(rl + 8) * 132 + c + 1] = acc[i][j][3] + b1;
            }
        }
        __syncthreads();
        const int bb = blockIdx.y / 3;
        const int l0tok = (blockIdx.y % 3) * 128;
#pragma unroll
        for (int it = 0; it < 8; it++) {
            int idx = it * 256 + tid;
            int dl = idx & 127;
            int tb = (idx >> 7) * 8;
            float v[8];
#pragma unroll
            for (int u = 0; u < 8; u++) v[u] = s[(tb + u) * 132 + dl];
            int tok0 = l0tok + tb;
            size_t tile = (size_t)((bb * 3 + (n0 >> 7)) * 12 + (tok0 >> 5)) * TILE_U32;
            int p0 = (tok0 & 31) >> 1;
#pragma unroll
            for (int pp = 0; pp < 4; pp++) {
                uint32_t h, l;
                splitpack(v[2 * pp], v[2 * pp + 1], h, l);
                size_t o = tile + (offB(dl, p0 + pp) >> 2);
                g_Vth[o] = h; g_Vtl[o] = l;
            }
        }
    } else if (MODE == 1) {
        float* So = g_S + (size_t)b * BSTRIDE;
#pragma unroll
        for (int i = 0; i < 4; i++) {
            const int r0 = m0 + wm * 64 + i * 16 + g;
#pragma unroll
            for (int j = 0; j < 4; j++) {
                const int c0 = n0 + wn * 32 + j * 8 + t * 2;
                *(float2*)&So[(size_t)r0 * 384 + c0] =
                    make_float2(acc[i][j][0] * INV_SQRT_D, acc[i][j][1] * INV_SQRT_D);
                *(float2*)&So[(size_t)(r0 + 8) * 384 + c0] =
                    make_float2(acc[i][j][2] * INV_SQRT_D, acc[i][j][3] * INV_SQRT_D);
            }
        }
    } else {
        float* Oo = outp + (size_t)b * BSTRIDE;
#pragma unroll
        for (int i = 0; i < 4; i++) {
            const int r0 = m0 + wm * 64 + i * 16 + g;
#pragma unroll
            for (int j = 0; j < 4; j++) {
                const int c0 = n0 + wn * 32 + j * 8 + t * 2;
                *(float2*)&Oo[(size_t)r0 * 384 + c0] =
                    make_float2(acc[i][j][0], acc[i][j][1]);
                *(float2*)&Oo[(size_t)(r0 + 8) * 384 + c0] =
                    make_float2(acc[i][j][2], acc[i][j][3]);
            }
        }
    }
}

// ---------------------------------------------------------------------------
// Softmax: warp/row, index-based causal mask, writes P as fragment tiles.
// ---------------------------------------------------------------------------
__global__ __launch_bounds__(256) void softmax_kernel()
{
    const int row = blockIdx.x * 8 + (threadIdx.x >> 5);   // 0..98303
    const int lane = threadIdx.x & 31;
    const int q = row % 384;
    const float* p = g_S + (size_t)row * 384 + lane * 12;

    float v[12];
    *(float4*)&v[0] = *(const float4*)(p);
    *(float4*)&v[4] = *(const float4*)(p + 4);
    *(float4*)&v[8] = *(const float4*)(p + 8);

    const int kb = lane * 12;
#pragma unroll
    for (int j = 0; j < 12; j++)
        if (kb + j > q) v[j] = -1e30f;

    float mx = -1e30f;
#pragma unroll
    for (int j = 0; j < 12; j++) mx = fmaxf(mx, v[j]);
#pragma unroll
    for (int o = 16; o > 0; o >>= 1)
        mx = fmaxf(mx, __shfl_xor_sync(0xffffffffu, mx, o));

    float sum = 0.0f;
#pragma unroll
    for (int j = 0; j < 12; j++) { v[j] = expf(v[j] - mx); sum += v[j]; }
#pragma unroll
    for (int o = 16; o > 0; o >>= 1)
        sum += __shfl_xor_sync(0xffffffffu, sum, o);

    const float inv = 1.0f / sum;
    const int rl = row & 127;
    const size_t tb0 = (size_t)(row >> 7) * 12;
#pragma unroll
    for (int pp = 0; pp < 6; pp++) {
        int kp = lane * 6 + pp;
        uint32_t h, l;
        splitpack(v[2 * pp] * inv, v[2 * pp + 1] * inv, h, l);
        size_t o = (tb0 + (kp >> 4)) * TILE_U32 + (offA(rl, kp & 15) >> 2);
        g_Ph[o] = h; g_Pl[o] = l;
    }
}

// ---------------------------------------------------------------------------
extern "C" void kernel_launch(void* const* d_in, const int* in_sizes, int n_in,
                              void* d_out, int out_size)
{
    const float* z  = (const float*)d_in[0];
    const float* Wq = (const float*)d_in[1];
    const float* bq = (const float*)d_in[2];
    const float* Wk = (const float*)d_in[3];
    const float* bk = (const float*)d_in[4];
    const float* Wv = (const float*)d_in[5];
    const float* bv = (const float*)d_in[6];
    float* out = (float*)d_out;

    cudaFuncSetAttribute(gemm<0>, cudaFuncAttributeMaxDynamicSharedMemorySize, SMEM_BYTES);
    cudaFuncSetAttribute(gemm<1>, cudaFuncAttributeMaxDynamicSharedMemorySize, SMEM_BYTES);
    cudaFuncSetAttribute(gemm<2>, cudaFuncAttributeMaxDynamicSharedMemorySize, SMEM_BYTES);

    dim3 blk(NTH);

    presplit_z<<<NPAIR / 256, blk>>>(z);
    presplit_w<<<(3 * 73728) / 256, blk>>>(Wq, Wk, Wv);

    gemm<0><<<dim3(9, 768), blk, SMEM_BYTES>>>(bq, bk, bv, nullptr);
    gemm<1><<<dim3(6, 256), blk, SMEM_BYTES>>>(nullptr, nullptr, nullptr, nullptr);
    softmax_kernel<<<(256 * 384) / 8, blk>>>();
    gemm<2><<<dim3(3, 3, 256), blk, SMEM_BYTES>>>(nullptr, nullptr, nullptr, out);
}

// round 7
// speedup vs baseline: 3.3617x; 1.0399x over previous
#include <cuda_runtime.h>
#include <cuda_bf16.h>
#include <stdint.h>

#define NTH 256
#define BSTRIDE 147456               // floats per batch (384*384)
static const float INV_SQRT_D = 0.05103103630798288f;

#define NPAIR 18874368               // 256*384*192
#define TILE_U32 2048                // uint32 per 128x32 fragment tile (8KB)
#define WTILES (36 * TILE_U32)       // 3 tiles x 12 kt

// fragment-ordered 128x32 operand tiles
__device__ uint32_t g_zh[NPAIR],  g_zl[NPAIR];    // z, offA layout
__device__ uint32_t g_Yh[NPAIR],  g_Yl[NPAIR];    // Y = z*(Wq^T Wk), offB layout
__device__ uint32_t g_Vth[NPAIR], g_Vtl[NPAIR];   // V transposed, offB
__device__ uint32_t g_Ph[NPAIR],  g_Pl[NPAIR];    // softmax(P), offA
__device__ float    g_S[37748736];
__device__ uint32_t g_wqTh[WTILES], g_wqTl[WTILES];  // Wq^T, offA (m=d,k=f)
__device__ uint32_t g_wkTh[WTILES], g_wkTl[WTILES];  // Wk^T, offB (n=e,k=f)
__device__ uint32_t g_wvh[WTILES],  g_wvl[WTILES];   // Wv rows, offB
__device__ uint32_t g_Abh[WTILES],  g_Abl[WTILES];   // A=Wq^T Wk, offB (n=e,k=d)
__device__ float    g_a2[384];                       // Wk^T bq
__device__ float    g_v[98304];                      // z . a2

#define NSTAGE 3
#define STAGE_BYTES 32768            // A_HI 8K | A_LO 8K | B_HI 8K | B_LO 8K
#define SMEM_BYTES (NSTAGE * STAGE_BYTES)   // 96KB -> 2 CTAs/SM

// fragment-order byte offset of (row r 0..127, k-pair p 0..15) in an 8KB tile
__device__ __forceinline__ int offA(int r, int p) {
    return ((p >> 3) << 12) + ((r >> 4) << 9) +
           (((r & 7) * 4 + (p & 3)) << 4) +
           (((p >> 2) & 1) << 3) + (((r >> 3) & 1) << 2);
}
__device__ __forceinline__ int offB(int n, int p) {
    return ((p >> 3) << 12) + ((n >> 3) << 8) +
           (((n & 7) * 4 + (p & 3)) << 3) + (((p >> 2) & 1) << 2);
}

#define MMA(d, a, b) \
    asm volatile("mma.sync.aligned.m16n8k16.row.col.f32.bf16.bf16.f32 " \
        "{%0,%1,%2,%3},{%4,%5,%6,%7},{%8,%9},{%0,%1,%2,%3};" \
        : "+f"((d)[0]), "+f"((d)[1]), "+f"((d)[2]), "+f"((d)[3]) \
        : "r"((a).x), "r"((a).y), "r"((a).z), "r"((a).w), \
          "r"((b).x), "r"((b).y))

#define CP16(sa, gp) \
    asm volatile("cp.async.cg.shared.global [%0], [%1], 16;" :: "r"(sa), "l"(gp))
#define CP_COMMIT() asm volatile("cp.async.commit_group;" ::: "memory")
#define CP_WAIT1()  asm volatile("cp.async.wait_group 1;" ::: "memory")

__device__ __forceinline__ uint32_t smem_u32(const void* p) {
    uint32_t a;
    asm("{ .reg .u64 t; cvta.to.shared.u64 t, %1; cvt.u32.u64 %0, t; }"
        : "=r"(a) : "l"(p));
    return a;
}

__device__ __forceinline__ void splitpack(float x, float y,
                                          uint32_t& hi, uint32_t& lo) {
    __nv_bfloat16 hx = __float2bfloat16(x);
    __nv_bfloat16 hy = __float2bfloat16(y);
    float lx = x - __bfloat162float(hx);
    float ly = y - __bfloat162float(hy);
    __nv_bfloat162 h2 = __halves2bfloat162(hx, hy);
    __nv_bfloat162 l2 = __floats2bfloat162_rn(lx, ly);
    hi = reinterpret_cast<uint32_t&>(h2);
    lo = reinterpret_cast<uint32_t&>(l2);
}

// ---------------- a2 = Wk^T bq ----------------
__global__ void a2_kernel(const float* __restrict__ Wk,
                          const float* __restrict__ bq) {
    int d = threadIdx.x;                 // 384 threads
    float s = 0.0f;
    for (int f = 0; f < 384; f++) s += Wk[(size_t)f * 384 + d] * bq[f];
    g_a2[d] = s;
}

// ---------------- presplit z (offA tiles) + fused v = z.a2 ----------------
__global__ __launch_bounds__(256) void presplit_z(const float* __restrict__ z) {
    const int row = blockIdx.x * 8 + (threadIdx.x >> 5);
    const int lane = threadIdx.x & 31;
    const float* p = z + (size_t)row * 384 + lane * 12;

    float v[12];
    *(float4*)&v[0] = *(const float4*)(p);
    *(float4*)&v[4] = *(const float4*)(p + 4);
    *(float4*)&v[8] = *(const float4*)(p + 8);

    float a[12];
    *(float4*)&a[0] = *(const float4*)(g_a2 + lane * 12);
    *(float4*)&a[4] = *(const float4*)(g_a2 + lane * 12 + 4);
    *(float4*)&a[8] = *(const float4*)(g_a2 + lane * 12 + 8);

    float dot = 0.0f;
#pragma unroll
    for (int j = 0; j < 12; j++) dot += v[j] * a[j];
#pragma unroll
    for (int o = 16; o > 0; o >>= 1)
        dot += __shfl_xor_sync(0xffffffffu, dot, o);
    if (lane == 0) g_v[row] = dot;

    const int rl = row & 127;
    const size_t tb0 = (size_t)(row >> 7) * 12;
#pragma unroll
    for (int p6 = 0; p6 < 6; p6++) {
        int kp = lane * 6 + p6;
        uint32_t h, l;
        splitpack(v[2 * p6], v[2 * p6 + 1], h, l);
        size_t o = (tb0 + (kp >> 4)) * TILE_U32 + (offA(rl, kp & 15) >> 2);
        g_zh[o] = h; g_zl[o] = l;
    }
}

// ---------------- presplit weights: WqT(offA), WkT(offB), Wv(offB) ----------
__global__ __launch_bounds__(256) void presplit_weights(
    const float* __restrict__ Wq, const float* __restrict__ Wk,
    const float* __restrict__ Wv)
{
    const int which = blockIdx.y;
    const int idx = blockIdx.x * 256 + threadIdx.x;   // < 73728
    if (which == 0) {
        int d = idx / 192, fp = idx % 192;
        float x = Wq[(size_t)(2 * fp) * 384 + d];
        float y = Wq[(size_t)(2 * fp + 1) * 384 + d];
        uint32_t h, l; splitpack(x, y, h, l);
        size_t o = (size_t)((d >> 7) * 12 + (fp >> 4)) * TILE_U32 +
                   (offA(d & 127, fp & 15) >> 2);
        g_wqTh[o] = h; g_wqTl[o] = l;
    } else if (which == 1) {
        int e = idx / 192, fp = idx % 192;
        float x = Wk[(size_t)(2 * fp) * 384 + e];
        float y = Wk[(size_t)(2 * fp + 1) * 384 + e];
        uint32_t h, l; splitpack(x, y, h, l);
        size_t o = (size_t)((e >> 7) * 12 + (fp >> 4)) * TILE_U32 +
                   (offB(e & 127, fp & 15) >> 2);
        g_wkTh[o] = h; g_wkTl[o] = l;
    } else {
        int ng = idx / 192, kp = idx % 192;
        float2 vv = *(const float2*)&Wv[(size_t)ng * 384 + kp * 2];
        uint32_t h, l; splitpack(vv.x, vv.y, h, l);
        size_t o = (size_t)((ng >> 7) * 12 + (kp >> 4)) * TILE_U32 +
                   (offB(ng & 127, kp & 15) >> 2);
        g_wvh[o] = h; g_wvl[o] = l;
    }
}

// ---------------------------------------------------------------------------
// Unified 3-stage tensor-core GEMM (128x128 tile, KC=32, split-bf16 3-term)
// MODE 0: Y & V projections grid(6,768)  | MODE 1: S^T = z Y^T grid(6,256)
// MODE 2: out = P V grid(3,3,256)        | MODE 3: A = Wq^T Wk grid(3,3)
// ---------------------------------------------------------------------------
template <int MODE>
__global__ __launch_bounds__(NTH, 2) void gemm(
    const float* __restrict__ bias, float* __restrict__ outp)
{
    extern __shared__ __align__(16) char sm[];
    const uint32_t smb = smem_u32(sm);
    const int tid = threadIdx.x;
    const int lane = tid & 31;
    const int wid = tid >> 5;
    const int wm = wid >> 2;
    const int wn = wid & 3;

    const uint32_t *Ah, *Al, *Bh, *Bl;
    int NKT, n0 = 0, m0 = 0, w = 0, mt = 0, b = 0;

    if (MODE == 0) {
        w = blockIdx.x / 3;                 // 0 = Y, 1 = V
        int nt = blockIdx.x % 3;
        n0 = nt * 128;
        Ah = g_zh + (size_t)blockIdx.y * 24576;
        Al = g_zl + (size_t)blockIdx.y * 24576;
        if (w == 0) { Bh = g_Abh + nt * 12 * TILE_U32; Bl = g_Abl + nt * 12 * TILE_U32; }
        else        { Bh = g_wvh + nt * 12 * TILE_U32; Bl = g_wvl + nt * 12 * TILE_U32; }
        NKT = 12;
    } else if (MODE == 1) {
        // S^T tiles: mt = k-token tile (rows), nt = q tile (cols); need mt <= nt
        const int mtab[6] = {0, 0, 0, 1, 1, 2};
        const int ntab[6] = {0, 1, 2, 1, 2, 2};
        mt = mtab[blockIdx.x];
        int nt = ntab[blockIdx.x];
        b = blockIdx.y;
        m0 = mt * 128; n0 = nt * 128;
        Ah = g_zh + (size_t)(b * 3 + mt) * 24576;
        Al = g_zl + (size_t)(b * 3 + mt) * 24576;
        Bh = g_Yh + (size_t)(b * 3 + nt) * 24576;
        Bl = g_Yl + (size_t)(b * 3 + nt) * 24576;
        NKT = 12;
    } else if (MODE == 2) {
        int nt = blockIdx.x; mt = blockIdx.y; b = blockIdx.z;
        m0 = mt * 128; n0 = nt * 128;
        Ah = g_Ph + (size_t)(b * 3 + mt) * 24576;
        Al = g_Pl + (size_t)(b * 3 + mt) * 24576;
        Bh = g_Vth + (size_t)(b * 3 + nt) * 24576;
        Bl = g_Vtl + (size_t)(b * 3 + nt) * 24576;
        NKT = (mt + 1) * 4;
    } else {
        int nt = blockIdx.x; mt = blockIdx.y;     // A[d,e]: m=d tile, n=e tile
        m0 = mt * 128; n0 = nt * 128;
        Ah = g_wqTh + (size_t)mt * 24576;
        Al = g_wqTl + (size_t)mt * 24576;
        Bh = g_wkTh + (size_t)nt * 24576;
        Bl = g_wkTl + (size_t)nt * 24576;
        NKT = 12;
    }

    auto issue = [&](int kt, int st) {
        const uint32_t d0 = smb + st * STAGE_BYTES + tid * 16;
        const int go = kt * TILE_U32 + tid * 4;
        CP16(d0,              Ah + go);  CP16(d0 + 4096,          Ah + go + 1024);
        CP16(d0 + 8192,       Al + go);  CP16(d0 + 8192 + 4096,   Al + go + 1024);
        CP16(d0 + 16384,      Bh + go);  CP16(d0 + 16384 + 4096,  Bh + go + 1024);
        CP16(d0 + 24576,      Bl + go);  CP16(d0 + 24576 + 4096,  Bl + go + 1024);
    };

    issue(0, 0); CP_COMMIT();
    issue(1, 1); CP_COMMIT();

    float acc[4][4][4];
#pragma unroll
    for (int i = 0; i < 4; i++)
#pragma unroll
        for (int j = 0; j < 4; j++)
#pragma unroll
            for (int r = 0; r < 4; r++) acc[i][j][r] = 0.0f;

    int cs = 0, is = 2;
    for (int kt = 0; kt < NKT; kt++) {
        CP_WAIT1();
        __syncthreads();
        if (kt + 2 < NKT) issue(kt + 2, is);
        CP_COMMIT();

        const char* base = sm + cs * STAGE_BYTES;
#pragma unroll
        for (int s = 0; s < 2; s++) {
            uint4 ah[4], al[4];
#pragma unroll
            for (int i = 0; i < 4; i++) {
                int off = s * 4096 + (wm * 4 + i) * 512 + lane * 16;
                ah[i] = *(const uint4*)(base + off);
                al[i] = *(const uint4*)(base + 8192 + off);
            }
#pragma unroll
            for (int j = 0; j < 4; j++) {
                int off = s * 4096 + (wn * 4 + j) * 256 + lane * 8;
                uint2 bh = *(const uint2*)(base + 16384 + off);
                uint2 bl = *(const uint2*)(base + 24576 + off);
                // term-major: same-acc reuse distance = 4 MMAs
#pragma unroll
                for (int i = 0; i < 4; i++) MMA(acc[i][j], ah[i], bh);
#pragma unroll
                for (int i = 0; i < 4; i++) MMA(acc[i][j], ah[i], bl);
#pragma unroll
                for (int i = 0; i < 4; i++) MMA(acc[i][j], al[i], bh);
            }
        }
        cs = (cs == 2) ? 0 : cs + 1;
        is = (is == 2) ? 0 : is + 1;
    }

    // ---- epilogues ----
    const int g = lane >> 2, t = lane & 3;

    if (MODE == 0 && w == 0) {
        // Y (no bias): write offB fragment tiles keyed by q-row-tile
        const size_t tb0 = (size_t)blockIdx.y * 12;
#pragma unroll
        for (int i = 0; i < 4; i++) {
            const int rl = wm * 64 + i * 16 + g;
#pragma unroll
            for (int j = 0; j < 4; j++) {
                const int c0 = n0 + wn * 32 + j * 8 + t * 2;
                uint32_t h0, l0, h1, l1;
                splitpack(acc[i][j][0], acc[i][j][1], h0, l0);
                splitpack(acc[i][j][2], acc[i][j][3], h1, l1);
                size_t tile = (tb0 + (c0 >> 5)) * TILE_U32;
                int p = (c0 & 31) >> 1;
                size_t o1 = tile + (offB(rl, p) >> 2);
                size_t o2 = tile + (offB(rl + 8, p) >> 2);
                g_Yh[o1] = h0; g_Yl[o1] = l0;
                g_Yh[o2] = h1; g_Yl[o2] = l1;
            }
        }
    } else if (MODE == 0) {
        // V: stage fp32 tile, transposed fragment write to Vt (offB)
        __syncthreads();
        float* s = (float*)sm;   // [128][132]
#pragma unroll
        for (int i = 0; i < 4; i++) {
            const int rl = wm * 64 + i * 16 + g;
#pragma unroll
            for (int j = 0; j < 4; j++) {
                const int c = wn * 32 + j * 8 + t * 2;
                float b0 = bias[n0 + c], b1 = bias[n0 + c + 1];
                s[rl * 132 + c]           = acc[i][j][0] + b0;
                s[rl * 132 + c + 1]       = acc[i][j][1] + b1;
                s[(rl + 8) * 132 + c]     = acc[i][j][2] + b0;
                s[(rl + 8) * 132 + c + 1] = acc[i][j][3] + b1;
            }
        }
        __syncthreads();
        const int bb = blockIdx.y / 3;
        const int l0tok = (blockIdx.y % 3) * 128;
#pragma unroll
        for (int it = 0; it < 8; it++) {
            int idx = it * 256 + tid;
            int dl = idx & 127;
            int tb = (idx >> 7) * 8;
            float v[8];
#pragma unroll
            for (int u = 0; u < 8; u++) v[u] = s[(tb + u) * 132 + dl];
            int tok0 = l0tok + tb;
            size_t tile = (size_t)((bb * 3 + (n0 >> 7)) * 12 + (tok0 >> 5)) * TILE_U32;
            int p0 = (tok0 & 31) >> 1;
#pragma unroll
            for (int pp = 0; pp < 4; pp++) {
                uint32_t h, l;
                splitpack(v[2 * pp], v[2 * pp + 1], h, l);
                size_t o = tile + (offB(dl, p0 + pp) >> 2);
                g_Vth[o] = h; g_Vtl[o] = l;
            }
        }
    } else if (MODE == 1) {
        // acc holds S^T[k=r0, q=c0]; store into S[q][k] raw (unscaled)
        float* So = g_S + (size_t)b * BSTRIDE;
#pragma unroll
        for (int i = 0; i < 4; i++) {
            const int r0 = m0 + wm * 64 + i * 16 + g;
#pragma unroll
            for (int j = 0; j < 4; j++) {
                const int c0 = n0 + wn * 32 + j * 8 + t * 2;
                So[(size_t)c0 * 384 + r0]           = acc[i][j][0];
                So[(size_t)(c0 + 1) * 384 + r0]     = acc[i][j][1];
                So[(size_t)c0 * 384 + r0 + 8]       = acc[i][j][2];
                So[(size_t)(c0 + 1) * 384 + r0 + 8] = acc[i][j][3];
            }
        }
    } else if (MODE == 2) {
        float* Oo = outp + (size_t)b * BSTRIDE;
#pragma unroll
        for (int i = 0; i < 4; i++) {
            const int r0 = m0 + wm * 64 + i * 16 + g;
#pragma unroll
            for (int j = 0; j < 4; j++) {
                const int c0 = n0 + wn * 32 + j * 8 + t * 2;
                *(float2*)&Oo[(size_t)r0 * 384 + c0] =
                    make_float2(acc[i][j][0], acc[i][j][1]);
                *(float2*)&Oo[(size_t)(r0 + 8) * 384 + c0] =
                    make_float2(acc[i][j][2], acc[i][j][3]);
            }
        }
    } else {
        // MODE 3: A[d,e] -> transpose-write g_Ab as offB (n=e, k=d)
        __syncthreads();
        float* s = (float*)sm;   // [128 d][132 e]
#pragma unroll
        for (int i = 0; i < 4; i++) {
            const int rl = wm * 64 + i * 16 + g;
#pragma unroll
            for (int j = 0; j < 4; j++) {
                const int c = wn * 32 + j * 8 + t * 2;
                s[rl * 132 + c]           = acc[i][j][0];
                s[rl * 132 + c + 1]       = acc[i][j][1];
                s[(rl + 8) * 132 + c]     = acc[i][j][2];
                s[(rl + 8) * 132 + c + 1] = acc[i][j][3];
            }
        }
        __syncthreads();
#pragma unroll
        for (int it = 0; it < 8; it++) {
            int idx = it * 256 + tid;
            int el = idx & 127;
            int db = (idx >> 7) * 8;
            float v[8];
#pragma unroll
            for (int u = 0; u < 8; u++) v[u] = s[(db + u) * 132 + el];
            int k0 = m0 + db;
            size_t tile = (size_t)((n0 >> 7) * 12 + (k0 >> 5)) * TILE_U32;
            int p0 = (k0 & 31) >> 1;
#pragma unroll
            for (int pp = 0; pp < 4; pp++) {
                uint32_t h, l;
                splitpack(v[2 * pp], v[2 * pp + 1], h, l);
                size_t o = tile + (offB(el, p0 + pp) >> 2);
                g_Abh[o] = h; g_Abl[o] = l;
            }
        }
    }
}

// ---------------------------------------------------------------------------
// Softmax: warp/row; adds v_k, scales, masks by index; writes P offA tiles.
// ---------------------------------------------------------------------------
__global__ __launch_bounds__(256) void softmax_kernel()
{
    const int row = blockIdx.x * 8 + (threadIdx.x >> 5);   // 0..98303
    const int lane = threadIdx.x & 31;
    const int q = row % 384;
    const int b = row / 384;
    const float* p = g_S + (size_t)row * 384 + lane * 12;
    const float* vr = g_v + (size_t)b * 384 + lane * 12;

    float v[12], vv[12];
    *(float4*)&v[0] = *(const float4*)(p);
    *(float4*)&v[4] = *(const float4*)(p + 4);
    *(float4*)&v[8] = *(const float4*)(p + 8);
    *(float4*)&vv[0] = *(const float4*)(vr);
    *(float4*)&vv[4] = *(const float4*)(vr + 4);
    *(float4*)&vv[8] = *(const float4*)(vr + 8);

    const int kb = lane * 12;
#pragma unroll
    for (int j = 0; j < 12; j++) {
        v[j] = (v[j] + vv[j]) * INV_SQRT_D;
        if (kb + j > q) v[j] = -1e30f;
    }

    float mx = -1e30f;
#pragma unroll
    for (int j = 0; j < 12; j++) mx = fmaxf(mx, v[j]);
#pragma unroll
    for (int o = 16; o > 0; o >>= 1)
        mx = fmaxf(mx, __shfl_xor_sync(0xffffffffu, mx, o));

    float sum = 0.0f;
#pragma unroll
    for (int j = 0; j < 12; j++) { v[j] = expf(v[j] - mx); sum += v[j]; }
#pragma unroll
    for (int o = 16; o > 0; o >>= 1)
        sum += __shfl_xor_sync(0xffffffffu, sum, o);

    const float inv = 1.0f / sum;
    const int rl = row & 127;
    const size_t tb0 = (size_t)(row >> 7) * 12;
#pragma unroll
    for (int pp = 0; pp < 6; pp++) {
        int kp = lane * 6 + pp;
        uint32_t h, l;
        splitpack(v[2 * pp] * inv, v[2 * pp + 1] * inv, h, l);
        size_t o = (tb0 + (kp >> 4)) * TILE_U32 + (offA(rl, kp & 15) >> 2);
        g_Ph[o] = h; g_Pl[o] = l;
    }
}

// ---------------------------------------------------------------------------
extern "C" void kernel_launch(void* const* d_in, const int* in_sizes, int n_in,
                              void* d_out, int out_size)
{
    const float* z  = (const float*)d_in[0];
    const float* Wq = (const float*)d_in[1];
    const float* bq = (const float*)d_in[2];
    const float* Wk = (const float*)d_in[3];
    const float* Wv = (const float*)d_in[5];
    const float* bv = (const float*)d_in[6];
    float* out = (float*)d_out;

    cudaFuncSetAttribute(gemm<0>, cudaFuncAttributeMaxDynamicSharedMemorySize, SMEM_BYTES);
    cudaFuncSetAttribute(gemm<1>, cudaFuncAttributeMaxDynamicSharedMemorySize, SMEM_BYTES);
    cudaFuncSetAttribute(gemm<2>, cudaFuncAttributeMaxDynamicSharedMemorySize, SMEM_BYTES);
    cudaFuncSetAttribute(gemm<3>, cudaFuncAttributeMaxDynamicSharedMemorySize, SMEM_BYTES);

    dim3 blk(NTH);

    a2_kernel<<<1, 384>>>(Wk, bq);
    presplit_z<<<12288, blk>>>(z);
    presplit_weights<<<dim3(288, 3), blk>>>(Wq, Wk, Wv);

    // A = Wq^T Wk (tiny)
    gemm<3><<<dim3(3, 3), blk, SMEM_BYTES>>>(nullptr, nullptr);

    // Y = z A  and  V = z Wv^T + bv
    gemm<0><<<dim3(6, 768), blk, SMEM_BYTES>>>(bv, nullptr);

    // S^T tiles = z Y^T (lower-triangle only), stored into S normally
    gemm<1><<<dim3(6, 256), blk, SMEM_BYTES>>>(nullptr, nullptr);

    // softmax with +v_k, index mask, /sqrt(D) -> P (offA fragment tiles)
    softmax_kernel<<<12288, blk>>>();

    // out = P V
    gemm<2><<<dim3(3, 3, 256), blk, SMEM_BYTES>>>(nullptr, out);
}